// round 4
// baseline (speedup 1.0000x reference)
#include <cuda_runtime.h>
#include <cuda_bf16.h>
#include <math.h>

#define BSZ 2
#define SEQ 2048
#define EMB 2048
#define NH  32
#define NKV 8
#define HD  64

// ---------------- scratch (static device memory; no allocs allowed) ----------
__device__ float g_q_lin[BSZ * SEQ * EMB];          // x@Wq  (B,S,H,D)
__device__ float g_q[BSZ * SEQ * EMB];              // rope'd q, (B,H,S,D)
__device__ float g_k_lin[BSZ * SEQ * NKV * HD];     // x@Wk  (B,S,KV,D)
__device__ float g_v_lin[BSZ * SEQ * NKV * HD];     // x@Wv  (B,S,KV,D)
__device__ float g_att[BSZ * SEQ * EMB];            // attn out (B,S,H,D)

// ---------------- fp32 SGEMM: C[M,N] = A[M,K] @ B[K,N], all row-major --------
// BM=BN=128, BK=16, 256 threads, 8x8 per thread. M%128==0, N%128==0, K%16==0.
__global__ __launch_bounds__(256) void sgemm_kernel(
    const float* __restrict__ A, const float* __restrict__ B,
    float* __restrict__ C, int M, int N, int K)
{
    __shared__ float As[16][128];   // transposed A tile
    __shared__ float Bs[16][128];

    const int tid = threadIdx.x;
    const int bx = blockIdx.x;      // N tile
    const int by = blockIdx.y;      // M tile
    const int tr = tid >> 4;        // 0..15
    const int tc = tid & 15;        // 0..15

    const int aRow = tid >> 2;          // 0..63
    const int aCol = (tid & 3) * 4;     // 0,4,8,12
    const int bRow = tid >> 5;          // 0..7
    const int bCol = (tid & 31) * 4;    // 0..124

    const float* Ab = A + (size_t)(by * 128) * K;
    const float* Bb = B + bx * 128;

    float acc[8][8];
#pragma unroll
    for (int i = 0; i < 8; i++)
#pragma unroll
        for (int j = 0; j < 8; j++) acc[i][j] = 0.f;

    for (int k0 = 0; k0 < K; k0 += 16) {
        float4 a0 = *(const float4*)(Ab + (size_t)aRow * K + k0 + aCol);
        float4 a1 = *(const float4*)(Ab + (size_t)(aRow + 64) * K + k0 + aCol);
        As[aCol + 0][aRow] = a0.x; As[aCol + 1][aRow] = a0.y;
        As[aCol + 2][aRow] = a0.z; As[aCol + 3][aRow] = a0.w;
        As[aCol + 0][aRow + 64] = a1.x; As[aCol + 1][aRow + 64] = a1.y;
        As[aCol + 2][aRow + 64] = a1.z; As[aCol + 3][aRow + 64] = a1.w;
        *(float4*)&Bs[bRow][bCol]     = *(const float4*)(Bb + (size_t)(k0 + bRow) * N + bCol);
        *(float4*)&Bs[bRow + 8][bCol] = *(const float4*)(Bb + (size_t)(k0 + bRow + 8) * N + bCol);
        __syncthreads();

#pragma unroll
        for (int kk = 0; kk < 16; kk++) {
            float ra[8], rb[8];
            *(float4*)&ra[0] = *(const float4*)&As[kk][tr * 8];
            *(float4*)&ra[4] = *(const float4*)&As[kk][tr * 8 + 4];
            *(float4*)&rb[0] = *(const float4*)&Bs[kk][tc * 8];
            *(float4*)&rb[4] = *(const float4*)&Bs[kk][tc * 8 + 4];
#pragma unroll
            for (int i = 0; i < 8; i++)
#pragma unroll
                for (int j = 0; j < 8; j++)
                    acc[i][j] += ra[i] * rb[j];
        }
        __syncthreads();
    }

#pragma unroll
    for (int i = 0; i < 8; i++) {
        float* Cp = C + (size_t)(by * 128 + tr * 8 + i) * N + bx * 128 + tc * 8;
        *(float4*)Cp       = make_float4(acc[i][0], acc[i][1], acc[i][2], acc[i][3]);
        *(float4*)(Cp + 4) = make_float4(acc[i][4], acc[i][5], acc[i][6], acc[i][7]);
    }
}

// ---------------- RoPE q: (B,S,H,D) -> (B,H,S,D) ----------------------------
__global__ void rope_q_kernel(const float* __restrict__ qin, float* __restrict__ qout,
                              const float* __restrict__ cosT, const float* __restrict__ sinT)
{
    int idx = blockIdx.x * blockDim.x + threadIdx.x;   // B*S*H*32 threads
    int d = idx & 31;
    int h = (idx >> 5) & 31;
    int s = (idx >> 10) & 2047;
    int b = idx >> 21;
    float cv = cosT[s * HD + d];
    float sv = sinT[s * HD + d];
    size_t i0 = ((size_t)(b * SEQ + s) * NH + h) * HD + d;
    float x1 = qin[i0], x2 = qin[i0 + 32];
    size_t o0 = ((size_t)(b * NH + h) * SEQ + s) * HD + d;
    qout[o0]      = x1 * cv - x2 * sv;
    qout[o0 + 32] = x2 * cv + x1 * sv;
}

// ---------------- RoPE k: (B,S,KV,D) -> (B,KV,S,D) (writes next_k) ----------
__global__ void rope_k_kernel(const float* __restrict__ kin, float* __restrict__ kout,
                              const float* __restrict__ cosT, const float* __restrict__ sinT)
{
    int idx = blockIdx.x * blockDim.x + threadIdx.x;   // B*S*KV*32 threads
    int d = idx & 31;
    int h = (idx >> 5) & 7;
    int s = (idx >> 8) & 2047;
    int b = idx >> 19;
    float cv = cosT[s * HD + d];
    float sv = sinT[s * HD + d];
    size_t i0 = ((size_t)(b * SEQ + s) * NKV + h) * HD + d;
    float x1 = kin[i0], x2 = kin[i0 + 32];
    size_t o0 = ((size_t)(b * NKV + h) * SEQ + s) * HD + d;
    kout[o0]      = x1 * cv - x2 * sv;
    kout[o0 + 32] = x2 * cv + x1 * sv;
}

// ---------------- V transpose: (B,S,KV,D) -> (B,KV,S,D) (writes next_v) -----
__global__ void vtrans_kernel(const float4* __restrict__ vin, float4* __restrict__ vout)
{
    int idx = blockIdx.x * blockDim.x + threadIdx.x;   // B*S*KV*16 float4
    int f = idx & 15;
    int h = (idx >> 4) & 7;
    int s = (idx >> 7) & 2047;
    int b = idx >> 18;
    vout[((size_t)(b * NKV + h) * SEQ + s) * (HD / 4) + f] =
        vin[((size_t)(b * SEQ + s) * NKV + h) * (HD / 4) + f];
}

// ---------------- causal flash attention ------------------------------------
// Q: (B,H,S,D) rope'd. K,V: (B,KV,S,D). O: (B,S,H,D).
// Block: 64 query rows of one head. 128 threads. Key tiles of 32.
__global__ __launch_bounds__(128) void flash_kernel(
    const float* __restrict__ Q, const float* __restrict__ Kg,
    const float* __restrict__ Vg, float* __restrict__ Og)
{
    __shared__ float Qt[64][64];    // [d][r]
    __shared__ float Kt[64][32];    // [d][j]
    __shared__ float Vs[32][64];    // [j][d]
    __shared__ float Ps[64][36];    // [r][j], padded

    const int qt = blockIdx.x;                 // query tile (64 rows)
    const int hh = blockIdx.y;                 // b*32+h
    const int b = hh >> 5, h = hh & 31, kvh = h >> 2;
    const int tid = threadIdx.x;

    const float* Qb = Q + ((size_t)((b * NH + h) * SEQ) + qt * 64) * HD;
    const float* Kb = Kg + (size_t)((b * NKV + kvh) * SEQ) * HD;
    const float* Vb = Vg + (size_t)((b * NKV + kvh) * SEQ) * HD;

    // load Q tile transposed
    {
        int r = tid >> 1, half = tid & 1;
#pragma unroll
        for (int i = 0; i < 8; i++) {
            int d = half * 32 + i * 4;
            float4 v = *(const float4*)(Qb + (size_t)r * HD + d);
            Qt[d + 0][r] = v.x; Qt[d + 1][r] = v.y;
            Qt[d + 2][r] = v.z; Qt[d + 3][r] = v.w;
        }
    }

    const int c  = tid & 7;     // col chunk (4 score cols / 8 out dims)
    const int rg = tid >> 3;    // 0..15
    const int r0 = rg * 4;
    const int dc = c * 8;

    float m[4], l[4], o[4][8];
#pragma unroll
    for (int i = 0; i < 4; i++) {
        m[i] = -1e30f; l[i] = 0.f;
#pragma unroll
        for (int j = 0; j < 8; j++) o[i][j] = 0.f;
    }

    const int ntiles = 2 * qt + 2;
    for (int kt = 0; kt < ntiles; kt++) {
        __syncthreads();
        {   // load K (transposed) and V tiles
            int j = tid >> 2, quarter = tid & 3;
            const float* Krow = Kb + (size_t)(kt * 32 + j) * HD;
            const float* Vrow = Vb + (size_t)(kt * 32 + j) * HD;
#pragma unroll
            for (int i = 0; i < 4; i++) {
                int d = quarter * 16 + i * 4;
                float4 kv = *(const float4*)(Krow + d);
                Kt[d + 0][j] = kv.x; Kt[d + 1][j] = kv.y;
                Kt[d + 2][j] = kv.z; Kt[d + 3][j] = kv.w;
                *(float4*)&Vs[j][d] = *(const float4*)(Vrow + d);
            }
        }
        __syncthreads();

        // S = Q K^T  (4 rows x 4 cols per thread)
        float s4[4][4];
#pragma unroll
        for (int i = 0; i < 4; i++)
#pragma unroll
            for (int j = 0; j < 4; j++) s4[i][j] = 0.f;

#pragma unroll 16
        for (int d = 0; d < 64; d++) {
            float4 qv = *(const float4*)&Qt[d][r0];
            float4 kv = *(const float4*)&Kt[d][c * 4];
            s4[0][0] += qv.x * kv.x; s4[0][1] += qv.x * kv.y; s4[0][2] += qv.x * kv.z; s4[0][3] += qv.x * kv.w;
            s4[1][0] += qv.y * kv.x; s4[1][1] += qv.y * kv.y; s4[1][2] += qv.y * kv.z; s4[1][3] += qv.y * kv.w;
            s4[2][0] += qv.z * kv.x; s4[2][1] += qv.z * kv.y; s4[2][2] += qv.z * kv.z; s4[2][3] += qv.z * kv.w;
            s4[3][0] += qv.w * kv.x; s4[3][1] += qv.w * kv.y; s4[3][2] += qv.w * kv.z; s4[3][3] += qv.w * kv.w;
        }

        const bool domask = (kt >= 2 * qt);
#pragma unroll
        for (int i = 0; i < 4; i++) {
            int row = qt * 64 + r0 + i;
            float sc[4];
#pragma unroll
            for (int j = 0; j < 4; j++) {
                sc[j] = s4[i][j] * 0.125f;          // 1/sqrt(64)
                if (domask && (kt * 32 + c * 4 + j > row)) sc[j] = -1e30f;
            }
            float mloc = fmaxf(fmaxf(sc[0], sc[1]), fmaxf(sc[2], sc[3]));
            mloc = fmaxf(mloc, __shfl_xor_sync(0xffffffffu, mloc, 1));
            mloc = fmaxf(mloc, __shfl_xor_sync(0xffffffffu, mloc, 2));
            mloc = fmaxf(mloc, __shfl_xor_sync(0xffffffffu, mloc, 4));
            float mnew  = fmaxf(m[i], mloc);
            float alpha = __expf(m[i] - mnew);
            float p0 = __expf(sc[0] - mnew), p1 = __expf(sc[1] - mnew);
            float p2 = __expf(sc[2] - mnew), p3 = __expf(sc[3] - mnew);
            float ps = p0 + p1 + p2 + p3;
            ps += __shfl_xor_sync(0xffffffffu, ps, 1);
            ps += __shfl_xor_sync(0xffffffffu, ps, 2);
            ps += __shfl_xor_sync(0xffffffffu, ps, 4);
            l[i] = l[i] * alpha + ps;
            m[i] = mnew;
#pragma unroll
            for (int j = 0; j < 8; j++) o[i][j] *= alpha;
            *(float4*)&Ps[r0 + i][c * 4] = make_float4(p0, p1, p2, p3);
        }
        __syncthreads();

        // O += P @ V  (4 rows x 8 dims per thread)
#pragma unroll 8
        for (int j = 0; j < 32; j++) {
            float4 va = *(const float4*)&Vs[j][dc];
            float4 vb = *(const float4*)&Vs[j][dc + 4];
#pragma unroll
            for (int i = 0; i < 4; i++) {
                float p = Ps[r0 + i][j];
                o[i][0] += p * va.x; o[i][1] += p * va.y; o[i][2] += p * va.z; o[i][3] += p * va.w;
                o[i][4] += p * vb.x; o[i][5] += p * vb.y; o[i][6] += p * vb.z; o[i][7] += p * vb.w;
            }
        }
    }

    // normalize + write (B,S,H,D)
#pragma unroll
    for (int i = 0; i < 4; i++) {
        float inv = 1.f / l[i];
        int srow = qt * 64 + r0 + i;
        float* op = Og + ((size_t)(b * SEQ + srow) * NH + h) * HD + dc;
        *(float4*)op       = make_float4(o[i][0] * inv, o[i][1] * inv, o[i][2] * inv, o[i][3] * inv);
        *(float4*)(op + 4) = make_float4(o[i][4] * inv, o[i][5] * inv, o[i][6] * inv, o[i][7] * inv);
    }
}

// ---------------- launch -----------------------------------------------------
extern "C" void kernel_launch(void* const* d_in, const int* in_sizes, int n_in,
                              void* d_out, int out_size)
{
    const float* x    = (const float*)d_in[0];
    // d_in[1] = mask (causal, recomputed analytically)
    const float* cosT = (const float*)d_in[2];
    const float* sinT = (const float*)d_in[3];
    const float* Wq   = (const float*)d_in[4];
    const float* Wk   = (const float*)d_in[5];
    const float* Wv   = (const float*)d_in[6];
    const float* Wo   = (const float*)d_in[7];

    float* out = (float*)d_out;                         // (B,S,E)
    float* nk  = out + (size_t)BSZ * SEQ * EMB;         // (B,KV,S,D)
    float* nv  = nk + (size_t)BSZ * NKV * SEQ * HD;     // (B,KV,S,D)

    float *q_lin, *q, *k_lin, *v_lin, *att;
    cudaGetSymbolAddress((void**)&q_lin, g_q_lin);
    cudaGetSymbolAddress((void**)&q,     g_q);
    cudaGetSymbolAddress((void**)&k_lin, g_k_lin);
    cudaGetSymbolAddress((void**)&v_lin, g_v_lin);
    cudaGetSymbolAddress((void**)&att,   g_att);

    const int M = BSZ * SEQ;

    // projections
    sgemm_kernel<<<dim3(EMB / 128, M / 128), 256>>>(x, Wq, q_lin, M, EMB, EMB);
    sgemm_kernel<<<dim3((NKV * HD) / 128, M / 128), 256>>>(x, Wk, k_lin, M, NKV * HD, EMB);
    sgemm_kernel<<<dim3((NKV * HD) / 128, M / 128), 256>>>(x, Wv, v_lin, M, NKV * HD, EMB);

    // rope + layout transforms (k/v land directly in d_out as next_k/next_v)
    rope_q_kernel<<<(BSZ * SEQ * NH * 32) / 256, 256>>>(q_lin, q, cosT, sinT);
    rope_k_kernel<<<(BSZ * SEQ * NKV * 32) / 256, 256>>>(k_lin, nk, cosT, sinT);
    vtrans_kernel<<<(BSZ * SEQ * NKV * 16) / 256, 256>>>((const float4*)v_lin, (float4*)nv);

    // attention
    flash_kernel<<<dim3(SEQ / 64, BSZ * NH), 128>>>(q, nk, nv, att);

    // output projection
    sgemm_kernel<<<dim3(EMB / 128, M / 128), 256>>>(att, Wo, out, M, EMB, EMB);
}

// round 7
// speedup vs baseline: 1.3875x; 1.3875x over previous
#include <cuda_runtime.h>
#include <cuda_bf16.h>
#include <math.h>
#include <stdint.h>

#define BSZ 2
#define SEQ 2048
#define EMB 2048
#define NH  32
#define NKV 8
#define HD  64
#define KVD (NKV * HD)   // 512

// ---------------- scratch (static device memory; no allocs allowed) ----------
__device__ float g_q_lin[BSZ * SEQ * EMB];          // x@Wq  (B,S,H,D)
__device__ float g_q[BSZ * SEQ * EMB];              // rope'd q, (B,H,S,D)
__device__ float g_k_lin[BSZ * SEQ * KVD];          // x@Wk  (B,S,KV,D)
__device__ float g_v_lin[BSZ * SEQ * KVD];          // x@Wv  (B,S,KV,D)
__device__ float g_att[BSZ * SEQ * EMB];            // attn out (B,S,H,D)

// bf16 split buffers
__device__ __nv_bfloat16 g_x_hi[BSZ * SEQ * EMB];
__device__ __nv_bfloat16 g_x_lo[BSZ * SEQ * EMB];
__device__ __nv_bfloat16 g_a_hi[BSZ * SEQ * EMB];
__device__ __nv_bfloat16 g_a_lo[BSZ * SEQ * EMB];
__device__ __nv_bfloat16 g_wq_h[EMB * EMB];
__device__ __nv_bfloat16 g_wq_l[EMB * EMB];
__device__ __nv_bfloat16 g_wo_h[EMB * EMB];
__device__ __nv_bfloat16 g_wo_l[EMB * EMB];
__device__ __nv_bfloat16 g_wk_h[KVD * EMB];
__device__ __nv_bfloat16 g_wk_l[KVD * EMB];
__device__ __nv_bfloat16 g_wv_h[KVD * EMB];
__device__ __nv_bfloat16 g_wv_l[KVD * EMB];

// ======================= helpers =============================================
__device__ __forceinline__ uint32_t cvta_smem(const void* p) {
    uint32_t a;
    asm("{ .reg .u64 t; cvta.to.shared.u64 t, %1; cvt.u32.u64 %0, t; }"
        : "=r"(a) : "l"(p));
    return a;
}

__device__ __forceinline__ void ldsm_x4(uint32_t& r0, uint32_t& r1,
                                        uint32_t& r2, uint32_t& r3, uint32_t addr) {
    asm volatile("ldmatrix.sync.aligned.m8n8.x4.shared.b16 {%0,%1,%2,%3}, [%4];"
                 : "=r"(r0), "=r"(r1), "=r"(r2), "=r"(r3) : "r"(addr));
}

__device__ __forceinline__ void mma_bf16(float& d0, float& d1, float& d2, float& d3,
                                         uint32_t a0, uint32_t a1, uint32_t a2, uint32_t a3,
                                         uint32_t b0, uint32_t b1) {
    asm volatile(
        "mma.sync.aligned.m16n8k16.row.col.f32.bf16.bf16.f32 "
        "{%0,%1,%2,%3}, {%4,%5,%6,%7}, {%8,%9}, {%0,%1,%2,%3};"
        : "+f"(d0), "+f"(d1), "+f"(d2), "+f"(d3)
        : "r"(a0), "r"(a1), "r"(a2), "r"(a3), "r"(b0), "r"(b1));
}

// ============ split conversion: fp32 -> (hi bf16, lo bf16) ===================
__global__ void split_kernel(const float4* __restrict__ in,
                             __nv_bfloat16* __restrict__ hi,
                             __nv_bfloat16* __restrict__ lo)
{
    int i = blockIdx.x * blockDim.x + threadIdx.x;
    float4 v = in[i];
    __nv_bfloat16 h[4], l[4];
    h[0] = __float2bfloat16(v.x); l[0] = __float2bfloat16(v.x - __bfloat162float(h[0]));
    h[1] = __float2bfloat16(v.y); l[1] = __float2bfloat16(v.y - __bfloat162float(h[1]));
    h[2] = __float2bfloat16(v.z); l[2] = __float2bfloat16(v.z - __bfloat162float(h[2]));
    h[3] = __float2bfloat16(v.w); l[3] = __float2bfloat16(v.w - __bfloat162float(h[3]));
    *(uint2*)&hi[(size_t)i * 4] = *(uint2*)h;
    *(uint2*)&lo[(size_t)i * 4] = *(uint2*)l;
}

// ===== weight transpose + split: W[K,N] fp32 -> Wt_hi/lo [N,K] bf16 ==========
__global__ void wsplit_t_kernel(const float* __restrict__ W,
                                __nv_bfloat16* __restrict__ Th,
                                __nv_bfloat16* __restrict__ Tl,
                                int K, int N)
{
    __shared__ float tile[32][33];
    int n0 = blockIdx.x * 32, k0 = blockIdx.y * 32;
    int tx = threadIdx.x, ty = threadIdx.y;   // 32 x 8
#pragma unroll
    for (int i = 0; i < 4; i++)
        tile[ty + 8 * i][tx] = W[(size_t)(k0 + ty + 8 * i) * N + n0 + tx];
    __syncthreads();
#pragma unroll
    for (int i = 0; i < 4; i++) {
        float v = tile[tx][ty + 8 * i];
        __nv_bfloat16 h = __float2bfloat16(v);
        __nv_bfloat16 l = __float2bfloat16(v - __bfloat162float(h));
        size_t o = (size_t)(n0 + ty + 8 * i) * K + k0 + tx;
        Th[o] = h;
        Tl[o] = l;
    }
}

// ====== mma.sync GEMM: C[M,N] = A[M,K] @ W[K,N], 3-term bf16 split ===========
// A split: Ah/Al [M,K] bf16 row-major. W pre-transposed+split: Bh/Bl [N,K] bf16.
// CTA tile 128x128, BK=32, 256 threads (2x4 warps, 64x32 per warp), dbl-buffer.
#define KPAD 40          // b16 elements per smem row (80 B, conflict-free ldsm)
#define ROWB 80          // bytes per smem row
#define TILE_SB (128 * ROWB)        // 10240 B per tile
#define STAGE_SB (4 * TILE_SB)      // Ah, Al, Bh, Bl = 40960 B

__global__ void __launch_bounds__(256) gemm_mma_kernel(
    const __nv_bfloat16* __restrict__ Ah, const __nv_bfloat16* __restrict__ Al,
    const __nv_bfloat16* __restrict__ Bh, const __nv_bfloat16* __restrict__ Bl,
    float* __restrict__ C, int M, int N, int K)
{
    extern __shared__ char dsm[];
    const int tid = threadIdx.x;
    const int wid = tid >> 5, lane = tid & 31;
    const int wm = wid >> 2, wn = wid & 3;     // 2 x 4 warp grid
    const int mT = blockIdx.y, nT = blockIdx.x;

    const uint32_t sbase = cvta_smem(dsm);

    // ---- global load mapping: per tile, 512 uint4; thread does 2 consecutive
    const int gr  = tid >> 1;            // row 0..127
    const int gk  = (tid & 1) * 2;       // kchunk 0 or 2 (each chunk = 8 b16)
    const __nv_bfloat16* srcs[4] = {
        Ah + (size_t)(mT * 128 + gr) * K,
        Al + (size_t)(mT * 128 + gr) * K,
        Bh + (size_t)(nT * 128 + gr) * K,
        Bl + (size_t)(nT * 128 + gr) * K
    };
    const uint32_t sdst = gr * ROWB + gk * 16;   // byte offset within tile

    float acc[4][4][4];
#pragma unroll
    for (int i = 0; i < 4; i++)
#pragma unroll
        for (int j = 0; j < 4; j++)
#pragma unroll
            for (int v = 0; v < 4; v++) acc[i][j][v] = 0.f;

    // ---- ldmatrix per-lane addresses (byte offsets within a tile)
    const int l8 = lane & 7, mi = lane >> 3;
    // A: mfrag i -> row = wm*64 + i*16 + l8 + (mi&1)*8, col = k16*16 + (mi>>1)*8
    const uint32_t a_off = (uint32_t)(wm * 64 + l8 + ((mi & 1) << 3)) * ROWB
                         + ((mi >> 1) << 3) * 2;
    // B: npair p -> row = wn*32 + p*16 + l8 + (mi&1)*8, same cols
    const uint32_t b_off = (uint32_t)(wn * 32 + l8 + ((mi & 1) << 3)) * ROWB
                         + ((mi >> 1) << 3) * 2;

    const int nch = K >> 5;   // BK = 32

    // prologue: load stage 0
    {
        const int k0 = 0;
#pragma unroll
        for (int t = 0; t < 4; t++) {
            uint4 v0 = *(const uint4*)(srcs[t] + k0 + gk * 8);
            uint4 v1 = *(const uint4*)(srcs[t] + k0 + gk * 8 + 8);
            uint32_t a = sbase + t * TILE_SB + sdst;
            asm volatile("st.shared.v4.b32 [%0], {%1,%2,%3,%4};"
                         :: "r"(a), "r"(v0.x), "r"(v0.y), "r"(v0.z), "r"(v0.w) : "memory");
            asm volatile("st.shared.v4.b32 [%0], {%1,%2,%3,%4};"
                         :: "r"(a + 16), "r"(v1.x), "r"(v1.y), "r"(v1.z), "r"(v1.w) : "memory");
        }
    }
    __syncthreads();

    for (int ch = 0; ch < nch; ch++) {
        const uint32_t stage = sbase + (ch & 1) * STAGE_SB;

        // prefetch next stage to regs
        uint4 pre[4][2];
        const bool more = (ch + 1 < nch);
        if (more) {
            const int k0 = (ch + 1) << 5;
#pragma unroll
            for (int t = 0; t < 4; t++) {
                pre[t][0] = *(const uint4*)(srcs[t] + k0 + gk * 8);
                pre[t][1] = *(const uint4*)(srcs[t] + k0 + gk * 8 + 8);
            }
        }

        // compute current stage: two k16 steps
#pragma unroll
        for (int k16 = 0; k16 < 2; k16++) {
            const uint32_t kb = k16 * 32;   // 16 b16 = 32 bytes
            uint32_t ah[4][4], al[4][4];
#pragma unroll
            for (int i = 0; i < 4; i++) {
                uint32_t addr = stage + a_off + (uint32_t)(i * 16) * ROWB + kb;
                ldsm_x4(ah[i][0], ah[i][1], ah[i][2], ah[i][3], addr);
                ldsm_x4(al[i][0], al[i][1], al[i][2], al[i][3], addr + TILE_SB);
            }
            uint32_t bh[4][2], bl[4][2];
#pragma unroll
            for (int p = 0; p < 2; p++) {
                uint32_t addr = stage + 2 * TILE_SB + b_off + (uint32_t)(p * 16) * ROWB + kb;
                uint32_t r0, r1, r2, r3;
                ldsm_x4(r0, r1, r2, r3, addr);
                bh[2 * p][0] = r0; bh[2 * p][1] = r2;
                bh[2 * p + 1][0] = r1; bh[2 * p + 1][1] = r3;
                ldsm_x4(r0, r1, r2, r3, addr + TILE_SB);
                bl[2 * p][0] = r0; bl[2 * p][1] = r2;
                bl[2 * p + 1][0] = r1; bl[2 * p + 1][1] = r3;
            }
#pragma unroll
            for (int i = 0; i < 4; i++)
#pragma unroll
                for (int j = 0; j < 4; j++) {
                    float* d = acc[i][j];
                    mma_bf16(d[0], d[1], d[2], d[3],
                             ah[i][0], ah[i][1], ah[i][2], ah[i][3],
                             bh[j][0], bh[j][1]);
                    mma_bf16(d[0], d[1], d[2], d[3],
                             ah[i][0], ah[i][1], ah[i][2], ah[i][3],
                             bl[j][0], bl[j][1]);
                    mma_bf16(d[0], d[1], d[2], d[3],
                             al[i][0], al[i][1], al[i][2], al[i][3],
                             bh[j][0], bh[j][1]);
                }
        }

        if (more) {
            __syncthreads();   // everyone done reading the buffer we overwrite
            const uint32_t nstage = sbase + ((ch + 1) & 1) * STAGE_SB;
#pragma unroll
            for (int t = 0; t < 4; t++) {
                uint32_t a = nstage + t * TILE_SB + sdst;
                asm volatile("st.shared.v4.b32 [%0], {%1,%2,%3,%4};"
                             :: "r"(a), "r"(pre[t][0].x), "r"(pre[t][0].y),
                                "r"(pre[t][0].z), "r"(pre[t][0].w) : "memory");
                asm volatile("st.shared.v4.b32 [%0], {%1,%2,%3,%4};"
                             :: "r"(a + 16), "r"(pre[t][1].x), "r"(pre[t][1].y),
                                "r"(pre[t][1].z), "r"(pre[t][1].w) : "memory");
            }
            __syncthreads();
        }
    }

    // epilogue: direct stores, d-frag layout (row = l/4, col = (l%4)*2)
    const int er = lane >> 2, ec = (lane & 3) * 2;
    float* Cb = C + (size_t)(mT * 128 + wm * 64 + er) * N + nT * 128 + wn * 32 + ec;
#pragma unroll
    for (int i = 0; i < 4; i++)
#pragma unroll
        for (int j = 0; j < 4; j++) {
            float* p0 = Cb + (size_t)(i * 16) * N + j * 8;
            *(float2*)p0                      = make_float2(acc[i][j][0], acc[i][j][1]);
            *(float2*)(p0 + (size_t)8 * N)    = make_float2(acc[i][j][2], acc[i][j][3]);
        }
}

// ---------------- RoPE q: (B,S,H,D) -> (B,H,S,D) ----------------------------
__global__ void rope_q_kernel(const float* __restrict__ qin, float* __restrict__ qout,
                              const float* __restrict__ cosT, const float* __restrict__ sinT)
{
    int idx = blockIdx.x * blockDim.x + threadIdx.x;
    int d = idx & 31;
    int h = (idx >> 5) & 31;
    int s = (idx >> 10) & 2047;
    int b = idx >> 21;
    float cv = cosT[s * HD + d];
    float sv = sinT[s * HD + d];
    size_t i0 = ((size_t)(b * SEQ + s) * NH + h) * HD + d;
    float x1 = qin[i0], x2 = qin[i0 + 32];
    size_t o0 = ((size_t)(b * NH + h) * SEQ + s) * HD + d;
    qout[o0]      = x1 * cv - x2 * sv;
    qout[o0 + 32] = x2 * cv + x1 * sv;
}

// ---------------- RoPE k: (B,S,KV,D) -> (B,KV,S,D) (writes next_k) ----------
__global__ void rope_k_kernel(const float* __restrict__ kin, float* __restrict__ kout,
                              const float* __restrict__ cosT, const float* __restrict__ sinT)
{
    int idx = blockIdx.x * blockDim.x + threadIdx.x;
    int d = idx & 31;
    int h = (idx >> 5) & 7;
    int s = (idx >> 8) & 2047;
    int b = idx >> 19;
    float cv = cosT[s * HD + d];
    float sv = sinT[s * HD + d];
    size_t i0 = ((size_t)(b * SEQ + s) * NKV + h) * HD + d;
    float x1 = kin[i0], x2 = kin[i0 + 32];
    size_t o0 = ((size_t)(b * NKV + h) * SEQ + s) * HD + d;
    kout[o0]      = x1 * cv - x2 * sv;
    kout[o0 + 32] = x2 * cv + x1 * sv;
}

// ---------------- V transpose: (B,S,KV,D) -> (B,KV,S,D) (writes next_v) -----
__global__ void vtrans_kernel(const float4* __restrict__ vin, float4* __restrict__ vout)
{
    int idx = blockIdx.x * blockDim.x + threadIdx.x;
    int f = idx & 15;
    int h = (idx >> 4) & 7;
    int s = (idx >> 7) & 2047;
    int b = idx >> 18;
    vout[((size_t)(b * NKV + h) * SEQ + s) * (HD / 4) + f] =
        vin[((size_t)(b * SEQ + s) * NKV + h) * (HD / 4) + f];
}

// ---------------- causal flash attention (fp32) ------------------------------
__global__ __launch_bounds__(128) void flash_kernel(
    const float* __restrict__ Q, const float* __restrict__ Kg,
    const float* __restrict__ Vg, float* __restrict__ Og)
{
    __shared__ float Qt[64][64];
    __shared__ float Kt[64][32];
    __shared__ float Vs[32][64];
    __shared__ float Ps[64][36];

    const int qt = blockIdx.x;
    const int hh = blockIdx.y;
    const int b = hh >> 5, h = hh & 31, kvh = h >> 2;
    const int tid = threadIdx.x;

    const float* Qb = Q + ((size_t)((b * NH + h) * SEQ) + qt * 64) * HD;
    const float* Kb = Kg + (size_t)((b * NKV + kvh) * SEQ) * HD;
    const float* Vb = Vg + (size_t)((b * NKV + kvh) * SEQ) * HD;

    {
        int r = tid >> 1, half = tid & 1;
#pragma unroll
        for (int i = 0; i < 8; i++) {
            int d = half * 32 + i * 4;
            float4 v = *(const float4*)(Qb + (size_t)r * HD + d);
            Qt[d + 0][r] = v.x; Qt[d + 1][r] = v.y;
            Qt[d + 2][r] = v.z; Qt[d + 3][r] = v.w;
        }
    }

    const int c  = tid & 7;
    const int rg = tid >> 3;
    const int r0 = rg * 4;
    const int dc = c * 8;

    float m[4], l[4], o[4][8];
#pragma unroll
    for (int i = 0; i < 4; i++) {
        m[i] = -1e30f; l[i] = 0.f;
#pragma unroll
        for (int j = 0; j < 8; j++) o[i][j] = 0.f;
    }

    const int ntiles = 2 * qt + 2;
    for (int kt = 0; kt < ntiles; kt++) {
        __syncthreads();
        {
            int j = tid >> 2, quarter = tid & 3;
            const float* Krow = Kb + (size_t)(kt * 32 + j) * HD;
            const float* Vrow = Vb + (size_t)(kt * 32 + j) * HD;
#pragma unroll
            for (int i = 0; i < 4; i++) {
                int d = quarter * 16 + i * 4;
                float4 kv = *(const float4*)(Krow + d);
                Kt[d + 0][j] = kv.x; Kt[d + 1][j] = kv.y;
                Kt[d + 2][j] = kv.z; Kt[d + 3][j] = kv.w;
                *(float4*)&Vs[j][d] = *(const float4*)(Vrow + d);
            }
        }
        __syncthreads();

        float s4[4][4];
#pragma unroll
        for (int i = 0; i < 4; i++)
#pragma unroll
            for (int j = 0; j < 4; j++) s4[i][j] = 0.f;

#pragma unroll 16
        for (int d = 0; d < 64; d++) {
            float4 qv = *(const float4*)&Qt[d][r0];
            float4 kv = *(const float4*)&Kt[d][c * 4];
            s4[0][0] += qv.x * kv.x; s4[0][1] += qv.x * kv.y; s4[0][2] += qv.x * kv.z; s4[0][3] += qv.x * kv.w;
            s4[1][0] += qv.y * kv.x; s4[1][1] += qv.y * kv.y; s4[1][2] += qv.y * kv.z; s4[1][3] += qv.y * kv.w;
            s4[2][0] += qv.z * kv.x; s4[2][1] += qv.z * kv.y; s4[2][2] += qv.z * kv.z; s4[2][3] += qv.z * kv.w;
            s4[3][0] += qv.w * kv.x; s4[3][1] += qv.w * kv.y; s4[3][2] += qv.w * kv.z; s4[3][3] += qv.w * kv.w;
        }

        const bool domask = (kt >= 2 * qt);
#pragma unroll
        for (int i = 0; i < 4; i++) {
            int row = qt * 64 + r0 + i;
            float sc[4];
#pragma unroll
            for (int j = 0; j < 4; j++) {
                sc[j] = s4[i][j] * 0.125f;
                if (domask && (kt * 32 + c * 4 + j > row)) sc[j] = -1e30f;
            }
            float mloc = fmaxf(fmaxf(sc[0], sc[1]), fmaxf(sc[2], sc[3]));
            mloc = fmaxf(mloc, __shfl_xor_sync(0xffffffffu, mloc, 1));
            mloc = fmaxf(mloc, __shfl_xor_sync(0xffffffffu, mloc, 2));
            mloc = fmaxf(mloc, __shfl_xor_sync(0xffffffffu, mloc, 4));
            float mnew  = fmaxf(m[i], mloc);
            float alpha = __expf(m[i] - mnew);
            float p0 = __expf(sc[0] - mnew), p1 = __expf(sc[1] - mnew);
            float p2 = __expf(sc[2] - mnew), p3 = __expf(sc[3] - mnew);
            float ps = p0 + p1 + p2 + p3;
            ps += __shfl_xor_sync(0xffffffffu, ps, 1);
            ps += __shfl_xor_sync(0xffffffffu, ps, 2);
            ps += __shfl_xor_sync(0xffffffffu, ps, 4);
            l[i] = l[i] * alpha + ps;
            m[i] = mnew;
#pragma unroll
            for (int j = 0; j < 8; j++) o[i][j] *= alpha;
            *(float4*)&Ps[r0 + i][c * 4] = make_float4(p0, p1, p2, p3);
        }
        __syncthreads();

#pragma unroll 8
        for (int j = 0; j < 32; j++) {
            float4 va = *(const float4*)&Vs[j][dc];
            float4 vb = *(const float4*)&Vs[j][dc + 4];
#pragma unroll
            for (int i = 0; i < 4; i++) {
                float p = Ps[r0 + i][j];
                o[i][0] += p * va.x; o[i][1] += p * va.y; o[i][2] += p * va.z; o[i][3] += p * va.w;
                o[i][4] += p * vb.x; o[i][5] += p * vb.y; o[i][6] += p * vb.z; o[i][7] += p * vb.w;
            }
        }
    }

#pragma unroll
    for (int i = 0; i < 4; i++) {
        float inv = 1.f / l[i];
        int srow = qt * 64 + r0 + i;
        float* op = Og + ((size_t)(b * SEQ + srow) * NH + h) * HD + dc;
        *(float4*)op       = make_float4(o[i][0] * inv, o[i][1] * inv, o[i][2] * inv, o[i][3] * inv);
        *(float4*)(op + 4) = make_float4(o[i][4] * inv, o[i][5] * inv, o[i][6] * inv, o[i][7] * inv);
    }
}

// ---------------- launch -----------------------------------------------------
extern "C" void kernel_launch(void* const* d_in, const int* in_sizes, int n_in,
                              void* d_out, int out_size)
{
    const float* x    = (const float*)d_in[0];
    const float* cosT = (const float*)d_in[2];
    const float* sinT = (const float*)d_in[3];
    const float* Wq   = (const float*)d_in[4];
    const float* Wk   = (const float*)d_in[5];
    const float* Wv   = (const float*)d_in[6];
    const float* Wo   = (const float*)d_in[7];

    float* out = (float*)d_out;                         // (B,S,E)
    float* nk  = out + (size_t)BSZ * SEQ * EMB;         // (B,KV,S,D)
    float* nv  = nk + (size_t)BSZ * NKV * SEQ * HD;     // (B,KV,S,D)

    float *q_lin, *q, *k_lin, *v_lin, *att;
    cudaGetSymbolAddress((void**)&q_lin, g_q_lin);
    cudaGetSymbolAddress((void**)&q,     g_q);
    cudaGetSymbolAddress((void**)&k_lin, g_k_lin);
    cudaGetSymbolAddress((void**)&v_lin, g_v_lin);
    cudaGetSymbolAddress((void**)&att,   g_att);

    __nv_bfloat16 *xh, *xl, *ah, *al;
    __nv_bfloat16 *wqh, *wql, *wkh, *wkl, *wvh, *wvl, *woh, *wol;
    cudaGetSymbolAddress((void**)&xh,  g_x_hi);
    cudaGetSymbolAddress((void**)&xl,  g_x_lo);
    cudaGetSymbolAddress((void**)&ah,  g_a_hi);
    cudaGetSymbolAddress((void**)&al,  g_a_lo);
    cudaGetSymbolAddress((void**)&wqh, g_wq_h);
    cudaGetSymbolAddress((void**)&wql, g_wq_l);
    cudaGetSymbolAddress((void**)&wkh, g_wk_h);
    cudaGetSymbolAddress((void**)&wkl, g_wk_l);
    cudaGetSymbolAddress((void**)&wvh, g_wv_h);
    cudaGetSymbolAddress((void**)&wvl, g_wv_l);
    cudaGetSymbolAddress((void**)&woh, g_wo_h);
    cudaGetSymbolAddress((void**)&wol, g_wo_l);

    cudaFuncSetAttribute(gemm_mma_kernel,
                         cudaFuncAttributeMaxDynamicSharedMemorySize, 2 * STAGE_SB);

    const int M = BSZ * SEQ;          // 4096
    const size_t NX = (size_t)M * EMB;

    // split x + weights (transpose+split)
    split_kernel<<<(int)(NX / 4 / 256), 256>>>((const float4*)x, xh, xl);
    wsplit_t_kernel<<<dim3(EMB / 32, EMB / 32), dim3(32, 8)>>>(Wq, wqh, wql, EMB, EMB);
    wsplit_t_kernel<<<dim3(KVD / 32, EMB / 32), dim3(32, 8)>>>(Wk, wkh, wkl, EMB, KVD);
    wsplit_t_kernel<<<dim3(KVD / 32, EMB / 32), dim3(32, 8)>>>(Wv, wvh, wvl, EMB, KVD);
    wsplit_t_kernel<<<dim3(EMB / 32, EMB / 32), dim3(32, 8)>>>(Wo, woh, wol, EMB, EMB);

    // projections on tensor cores (mma.sync bf16, 3-term split)
    gemm_mma_kernel<<<dim3(EMB / 128, M / 128), 256, 2 * STAGE_SB>>>(
        xh, xl, wqh, wql, q_lin, M, EMB, EMB);
    gemm_mma_kernel<<<dim3(KVD / 128, M / 128), 256, 2 * STAGE_SB>>>(
        xh, xl, wkh, wkl, k_lin, M, KVD, EMB);
    gemm_mma_kernel<<<dim3(KVD / 128, M / 128), 256, 2 * STAGE_SB>>>(
        xh, xl, wvh, wvl, v_lin, M, KVD, EMB);

    // rope + layout transforms (k/v land directly in d_out as next_k/next_v)
    rope_q_kernel<<<(BSZ * SEQ * NH * 32) / 256, 256>>>(q_lin, q, cosT, sinT);
    rope_k_kernel<<<(BSZ * SEQ * NKV * 32) / 256, 256>>>(k_lin, nk, cosT, sinT);
    vtrans_kernel<<<(BSZ * SEQ * NKV * 16) / 256, 256>>>((const float4*)v_lin, (float4*)nv);

    // attention
    flash_kernel<<<dim3(SEQ / 64, BSZ * NH), 128>>>(q, nk, nv, att);

    // output projection on tensor cores
    split_kernel<<<(int)(NX / 4 / 256), 256>>>((const float4*)att, ah, al);
    gemm_mma_kernel<<<dim3(EMB / 128, M / 128), 256, 2 * STAGE_SB>>>(
        ah, al, woh, wol, out, M, EMB, EMB);
}

// round 8
// speedup vs baseline: 2.1297x; 1.5350x over previous
#include <cuda_runtime.h>
#include <cuda_bf16.h>
#include <math.h>
#include <stdint.h>

#define BSZ 2
#define SEQ 2048
#define EMB 2048
#define NH  32
#define NKV 8
#define HD  64
#define KVD (NKV * HD)   // 512

// ---------------- scratch (static device memory; no allocs allowed) ----------
__device__ float g_q_lin[BSZ * SEQ * EMB];          // x@Wq  (B,S,H,D)
__device__ float g_k_lin[BSZ * SEQ * KVD];          // x@Wk  (B,S,KV,D)
__device__ float g_v_lin[BSZ * SEQ * KVD];          // x@Wv  (B,S,KV,D)

// bf16 split buffers
__device__ __nv_bfloat16 g_x_hi[BSZ * SEQ * EMB];
__device__ __nv_bfloat16 g_x_lo[BSZ * SEQ * EMB];
__device__ __nv_bfloat16 g_a_hi[BSZ * SEQ * EMB];   // attn out hi (B,S,H,D)
__device__ __nv_bfloat16 g_a_lo[BSZ * SEQ * EMB];   // attn out lo
__device__ __nv_bfloat16 g_qh[BSZ * SEQ * EMB];     // rope'd q hi (B,H,S,D)
__device__ __nv_bfloat16 g_ql[BSZ * SEQ * EMB];
__device__ __nv_bfloat16 g_kh[BSZ * SEQ * KVD];     // rope'd k hi (B,KV,S,D)
__device__ __nv_bfloat16 g_kl[BSZ * SEQ * KVD];
__device__ __nv_bfloat16 g_vh[BSZ * SEQ * KVD];     // v hi (B,KV,S,D)
__device__ __nv_bfloat16 g_vl[BSZ * SEQ * KVD];
__device__ __nv_bfloat16 g_wq_h[EMB * EMB];
__device__ __nv_bfloat16 g_wq_l[EMB * EMB];
__device__ __nv_bfloat16 g_wo_h[EMB * EMB];
__device__ __nv_bfloat16 g_wo_l[EMB * EMB];
__device__ __nv_bfloat16 g_wk_h[KVD * EMB];
__device__ __nv_bfloat16 g_wk_l[KVD * EMB];
__device__ __nv_bfloat16 g_wv_h[KVD * EMB];
__device__ __nv_bfloat16 g_wv_l[KVD * EMB];

// ======================= helpers =============================================
__device__ __forceinline__ uint32_t cvta_smem(const void* p) {
    uint32_t a;
    asm("{ .reg .u64 t; cvta.to.shared.u64 t, %1; cvt.u32.u64 %0, t; }"
        : "=r"(a) : "l"(p));
    return a;
}

__device__ __forceinline__ void ldsm_x4(uint32_t& r0, uint32_t& r1,
                                        uint32_t& r2, uint32_t& r3, uint32_t addr) {
    asm volatile("ldmatrix.sync.aligned.m8n8.x4.shared.b16 {%0,%1,%2,%3}, [%4];"
                 : "=r"(r0), "=r"(r1), "=r"(r2), "=r"(r3) : "r"(addr));
}

__device__ __forceinline__ void ldsm_x4_t(uint32_t& r0, uint32_t& r1,
                                          uint32_t& r2, uint32_t& r3, uint32_t addr) {
    asm volatile("ldmatrix.sync.aligned.m8n8.x4.trans.shared.b16 {%0,%1,%2,%3}, [%4];"
                 : "=r"(r0), "=r"(r1), "=r"(r2), "=r"(r3) : "r"(addr));
}

__device__ __forceinline__ void mma_bf16(float& d0, float& d1, float& d2, float& d3,
                                         uint32_t a0, uint32_t a1, uint32_t a2, uint32_t a3,
                                         uint32_t b0, uint32_t b1) {
    asm volatile(
        "mma.sync.aligned.m16n8k16.row.col.f32.bf16.bf16.f32 "
        "{%0,%1,%2,%3}, {%4,%5,%6,%7}, {%8,%9}, {%0,%1,%2,%3};"
        : "+f"(d0), "+f"(d1), "+f"(d2), "+f"(d3)
        : "r"(a0), "r"(a1), "r"(a2), "r"(a3), "r"(b0), "r"(b1));
}

__device__ __forceinline__ uint32_t pack_bf16(float a, float b) {
    __nv_bfloat162 t(__float2bfloat16(a), __float2bfloat16(b));
    return *(uint32_t*)&t;
}

// ============ split conversion: fp32 -> (hi bf16, lo bf16) ===================
__global__ void split_kernel(const float4* __restrict__ in,
                             __nv_bfloat16* __restrict__ hi,
                             __nv_bfloat16* __restrict__ lo)
{
    int i = blockIdx.x * blockDim.x + threadIdx.x;
    float4 v = in[i];
    __nv_bfloat16 h[4], l[4];
    h[0] = __float2bfloat16(v.x); l[0] = __float2bfloat16(v.x - __bfloat162float(h[0]));
    h[1] = __float2bfloat16(v.y); l[1] = __float2bfloat16(v.y - __bfloat162float(h[1]));
    h[2] = __float2bfloat16(v.z); l[2] = __float2bfloat16(v.z - __bfloat162float(h[2]));
    h[3] = __float2bfloat16(v.w); l[3] = __float2bfloat16(v.w - __bfloat162float(h[3]));
    *(uint2*)&hi[(size_t)i * 4] = *(uint2*)h;
    *(uint2*)&lo[(size_t)i * 4] = *(uint2*)l;
}

// ===== weight transpose + split: W[K,N] fp32 -> Wt_hi/lo [N,K] bf16 ==========
__global__ void wsplit_t_kernel(const float* __restrict__ W,
                                __nv_bfloat16* __restrict__ Th,
                                __nv_bfloat16* __restrict__ Tl,
                                int K, int N)
{
    __shared__ float tile[32][33];
    int n0 = blockIdx.x * 32, k0 = blockIdx.y * 32;
    int tx = threadIdx.x, ty = threadIdx.y;   // 32 x 8
#pragma unroll
    for (int i = 0; i < 4; i++)
        tile[ty + 8 * i][tx] = W[(size_t)(k0 + ty + 8 * i) * N + n0 + tx];
    __syncthreads();
#pragma unroll
    for (int i = 0; i < 4; i++) {
        float v = tile[tx][ty + 8 * i];
        __nv_bfloat16 h = __float2bfloat16(v);
        __nv_bfloat16 l = __float2bfloat16(v - __bfloat162float(h));
        size_t o = (size_t)(n0 + ty + 8 * i) * K + k0 + tx;
        Th[o] = h;
        Tl[o] = l;
    }
}

// ====== mma.sync GEMM: C[M,N] = A[M,K] @ W[K,N], 3-term bf16 split ===========
#define KPAD 40
#define ROWB 80
#define TILE_SB (128 * ROWB)
#define STAGE_SB (4 * TILE_SB)

__global__ void __launch_bounds__(256) gemm_mma_kernel(
    const __nv_bfloat16* __restrict__ Ah, const __nv_bfloat16* __restrict__ Al,
    const __nv_bfloat16* __restrict__ Bh, const __nv_bfloat16* __restrict__ Bl,
    float* __restrict__ C, int M, int N, int K)
{
    extern __shared__ char dsm[];
    const int tid = threadIdx.x;
    const int wid = tid >> 5, lane = tid & 31;
    const int wm = wid >> 2, wn = wid & 3;
    const int mT = blockIdx.y, nT = blockIdx.x;

    const uint32_t sbase = cvta_smem(dsm);

    const int gr  = tid >> 1;
    const int gk  = (tid & 1) * 2;
    const __nv_bfloat16* srcs[4] = {
        Ah + (size_t)(mT * 128 + gr) * K,
        Al + (size_t)(mT * 128 + gr) * K,
        Bh + (size_t)(nT * 128 + gr) * K,
        Bl + (size_t)(nT * 128 + gr) * K
    };
    const uint32_t sdst = gr * ROWB + gk * 16;

    float acc[4][4][4];
#pragma unroll
    for (int i = 0; i < 4; i++)
#pragma unroll
        for (int j = 0; j < 4; j++)
#pragma unroll
            for (int v = 0; v < 4; v++) acc[i][j][v] = 0.f;

    const int l8 = lane & 7, mi = lane >> 3;
    const uint32_t a_off = (uint32_t)(wm * 64 + l8 + ((mi & 1) << 3)) * ROWB
                         + ((mi >> 1) << 3) * 2;
    const uint32_t b_off = (uint32_t)(wn * 32 + l8 + ((mi & 1) << 3)) * ROWB
                         + ((mi >> 1) << 3) * 2;

    const int nch = K >> 5;

    {
#pragma unroll
        for (int t = 0; t < 4; t++) {
            uint4 v0 = *(const uint4*)(srcs[t] + gk * 8);
            uint4 v1 = *(const uint4*)(srcs[t] + gk * 8 + 8);
            uint32_t a = sbase + t * TILE_SB + sdst;
            asm volatile("st.shared.v4.b32 [%0], {%1,%2,%3,%4};"
                         :: "r"(a), "r"(v0.x), "r"(v0.y), "r"(v0.z), "r"(v0.w) : "memory");
            asm volatile("st.shared.v4.b32 [%0], {%1,%2,%3,%4};"
                         :: "r"(a + 16), "r"(v1.x), "r"(v1.y), "r"(v1.z), "r"(v1.w) : "memory");
        }
    }
    __syncthreads();

    for (int ch = 0; ch < nch; ch++) {
        const uint32_t stage = sbase + (ch & 1) * STAGE_SB;

        uint4 pre[4][2];
        const bool more = (ch + 1 < nch);
        if (more) {
            const int k0 = (ch + 1) << 5;
#pragma unroll
            for (int t = 0; t < 4; t++) {
                pre[t][0] = *(const uint4*)(srcs[t] + k0 + gk * 8);
                pre[t][1] = *(const uint4*)(srcs[t] + k0 + gk * 8 + 8);
            }
        }

#pragma unroll
        for (int k16 = 0; k16 < 2; k16++) {
            const uint32_t kb = k16 * 32;
            uint32_t ah[4][4], al[4][4];
#pragma unroll
            for (int i = 0; i < 4; i++) {
                uint32_t addr = stage + a_off + (uint32_t)(i * 16) * ROWB + kb;
                ldsm_x4(ah[i][0], ah[i][1], ah[i][2], ah[i][3], addr);
                ldsm_x4(al[i][0], al[i][1], al[i][2], al[i][3], addr + TILE_SB);
            }
            uint32_t bh[4][2], bl[4][2];
#pragma unroll
            for (int p = 0; p < 2; p++) {
                uint32_t addr = stage + 2 * TILE_SB + b_off + (uint32_t)(p * 16) * ROWB + kb;
                uint32_t r0, r1, r2, r3;
                ldsm_x4(r0, r1, r2, r3, addr);
                bh[2 * p][0] = r0; bh[2 * p][1] = r2;
                bh[2 * p + 1][0] = r1; bh[2 * p + 1][1] = r3;
                ldsm_x4(r0, r1, r2, r3, addr + TILE_SB);
                bl[2 * p][0] = r0; bl[2 * p][1] = r2;
                bl[2 * p + 1][0] = r1; bl[2 * p + 1][1] = r3;
            }
#pragma unroll
            for (int i = 0; i < 4; i++)
#pragma unroll
                for (int j = 0; j < 4; j++) {
                    float* d = acc[i][j];
                    mma_bf16(d[0], d[1], d[2], d[3],
                             ah[i][0], ah[i][1], ah[i][2], ah[i][3],
                             bh[j][0], bh[j][1]);
                    mma_bf16(d[0], d[1], d[2], d[3],
                             ah[i][0], ah[i][1], ah[i][2], ah[i][3],
                             bl[j][0], bl[j][1]);
                    mma_bf16(d[0], d[1], d[2], d[3],
                             al[i][0], al[i][1], al[i][2], al[i][3],
                             bh[j][0], bh[j][1]);
                }
        }

        if (more) {
            __syncthreads();
            const uint32_t nstage = sbase + ((ch + 1) & 1) * STAGE_SB;
#pragma unroll
            for (int t = 0; t < 4; t++) {
                uint32_t a = nstage + t * TILE_SB + sdst;
                asm volatile("st.shared.v4.b32 [%0], {%1,%2,%3,%4};"
                             :: "r"(a), "r"(pre[t][0].x), "r"(pre[t][0].y),
                                "r"(pre[t][0].z), "r"(pre[t][0].w) : "memory");
                asm volatile("st.shared.v4.b32 [%0], {%1,%2,%3,%4};"
                             :: "r"(a + 16), "r"(pre[t][1].x), "r"(pre[t][1].y),
                                "r"(pre[t][1].z), "r"(pre[t][1].w) : "memory");
            }
            __syncthreads();
        }
    }

    const int er = lane >> 2, ec = (lane & 3) * 2;
    float* Cb = C + (size_t)(mT * 128 + wm * 64 + er) * N + nT * 128 + wn * 32 + ec;
#pragma unroll
    for (int i = 0; i < 4; i++)
#pragma unroll
        for (int j = 0; j < 4; j++) {
            float* p0 = Cb + (size_t)(i * 16) * N + j * 8;
            *(float2*)p0                      = make_float2(acc[i][j][0], acc[i][j][1]);
            *(float2*)(p0 + (size_t)8 * N)    = make_float2(acc[i][j][2], acc[i][j][3]);
        }
}

// ---------------- RoPE q: (B,S,H,D) fp32 -> (B,H,S,D) bf16 hi/lo ------------
__global__ void rope_q_kernel(const float* __restrict__ qin,
                              __nv_bfloat16* __restrict__ qh,
                              __nv_bfloat16* __restrict__ ql,
                              const float* __restrict__ cosT, const float* __restrict__ sinT)
{
    int idx = blockIdx.x * blockDim.x + threadIdx.x;
    int d = idx & 31;
    int h = (idx >> 5) & 31;
    int s = (idx >> 10) & 2047;
    int b = idx >> 21;
    float cv = cosT[s * HD + d];
    float sv = sinT[s * HD + d];
    size_t i0 = ((size_t)(b * SEQ + s) * NH + h) * HD + d;
    float x1 = qin[i0], x2 = qin[i0 + 32];
    float v1 = x1 * cv - x2 * sv;
    float v2 = x2 * cv + x1 * sv;
    size_t o0 = ((size_t)(b * NH + h) * SEQ + s) * HD + d;
    __nv_bfloat16 h1 = __float2bfloat16(v1);
    __nv_bfloat16 h2 = __float2bfloat16(v2);
    qh[o0]      = h1;
    qh[o0 + 32] = h2;
    ql[o0]      = __float2bfloat16(v1 - __bfloat162float(h1));
    ql[o0 + 32] = __float2bfloat16(v2 - __bfloat162float(h2));
}

// ---------------- RoPE k: fp32 next_k + bf16 hi/lo (B,KV,S,D) ---------------
__global__ void rope_k_kernel(const float* __restrict__ kin, float* __restrict__ kout,
                              __nv_bfloat16* __restrict__ kh,
                              __nv_bfloat16* __restrict__ kl,
                              const float* __restrict__ cosT, const float* __restrict__ sinT)
{
    int idx = blockIdx.x * blockDim.x + threadIdx.x;
    int d = idx & 31;
    int h = (idx >> 5) & 7;
    int s = (idx >> 8) & 2047;
    int b = idx >> 19;
    float cv = cosT[s * HD + d];
    float sv = sinT[s * HD + d];
    size_t i0 = ((size_t)(b * SEQ + s) * NKV + h) * HD + d;
    float x1 = kin[i0], x2 = kin[i0 + 32];
    float v1 = x1 * cv - x2 * sv;
    float v2 = x2 * cv + x1 * sv;
    size_t o0 = ((size_t)(b * NKV + h) * SEQ + s) * HD + d;
    kout[o0]      = v1;
    kout[o0 + 32] = v2;
    __nv_bfloat16 h1 = __float2bfloat16(v1);
    __nv_bfloat16 h2 = __float2bfloat16(v2);
    kh[o0]      = h1;
    kh[o0 + 32] = h2;
    kl[o0]      = __float2bfloat16(v1 - __bfloat162float(h1));
    kl[o0 + 32] = __float2bfloat16(v2 - __bfloat162float(h2));
}

// --------- V transpose: fp32 next_v + bf16 hi/lo (B,KV,S,D) -----------------
__global__ void vtrans_kernel(const float4* __restrict__ vin, float4* __restrict__ vout,
                              __nv_bfloat16* __restrict__ vh,
                              __nv_bfloat16* __restrict__ vl)
{
    int idx = blockIdx.x * blockDim.x + threadIdx.x;
    int f = idx & 15;
    int h = (idx >> 4) & 7;
    int s = (idx >> 7) & 2047;
    int b = idx >> 18;
    float4 v = vin[((size_t)(b * SEQ + s) * NKV + h) * (HD / 4) + f];
    size_t o = ((size_t)(b * NKV + h) * SEQ + s) * (HD / 4) + f;
    vout[o] = v;
    __nv_bfloat16 hh[4], ll[4];
    hh[0] = __float2bfloat16(v.x); ll[0] = __float2bfloat16(v.x - __bfloat162float(hh[0]));
    hh[1] = __float2bfloat16(v.y); ll[1] = __float2bfloat16(v.y - __bfloat162float(hh[1]));
    hh[2] = __float2bfloat16(v.z); ll[2] = __float2bfloat16(v.z - __bfloat162float(hh[2]));
    hh[3] = __float2bfloat16(v.w); ll[3] = __float2bfloat16(v.w - __bfloat162float(hh[3]));
    *(uint2*)&vh[o * 4] = *(uint2*)hh;
    *(uint2*)&vl[o * 4] = *(uint2*)ll;
}

// ---------------- causal flash attention (mma.sync bf16 split) ---------------
// Q (B,H,S,D) hi/lo, K/V (B,KV,S,D) hi/lo. Out: hi/lo bf16 (B,S,H,D).
// Block: 64 q rows of one head, 4 warps (warp = 16 rows). Key tiles of 64.
#define FPITCH 72
#define FROWB  144
#define FTILE  (64 * FROWB)   // 9216 B per matrix tile
#define FSMEM  (6 * FTILE)    // Qh Ql Kh Kl Vh Vl = 55296 B

__global__ void __launch_bounds__(128) flash_mma_kernel(
    const __nv_bfloat16* __restrict__ Qh, const __nv_bfloat16* __restrict__ Ql,
    const __nv_bfloat16* __restrict__ Kh, const __nv_bfloat16* __restrict__ Kl,
    const __nv_bfloat16* __restrict__ Vh, const __nv_bfloat16* __restrict__ Vl,
    __nv_bfloat16* __restrict__ Oh, __nv_bfloat16* __restrict__ Ol)
{
    extern __shared__ char fsm[];
    const uint32_t sb  = cvta_smem(fsm);
    const uint32_t sQh = sb, sQl = sb + FTILE;
    const uint32_t sKh = sb + 2 * FTILE, sKl = sb + 3 * FTILE;
    const uint32_t sVh = sb + 4 * FTILE, sVl = sb + 5 * FTILE;

    const int qt = blockIdx.x, hh = blockIdx.y;
    const int b = hh >> 5, h = hh & 31, kvh = h >> 2;
    const int tid = threadIdx.x, wid = tid >> 5, lane = tid & 31;

    const __nv_bfloat16* Qhb = Qh + ((size_t)((b * NH + h) * SEQ) + qt * 64) * HD;
    const __nv_bfloat16* Qlb = Ql + ((size_t)((b * NH + h) * SEQ) + qt * 64) * HD;
    const __nv_bfloat16* Khb = Kh + (size_t)((b * NKV + kvh) * SEQ) * HD;
    const __nv_bfloat16* Klb = Kl + (size_t)((b * NKV + kvh) * SEQ) * HD;
    const __nv_bfloat16* Vhb = Vh + (size_t)((b * NKV + kvh) * SEQ) * HD;
    const __nv_bfloat16* Vlb = Vl + (size_t)((b * NKV + kvh) * SEQ) * HD;

    // load Q tiles (row = tid/2, half = tid&1 -> 32 b16 = 64 B)
    {
        const int r = tid >> 1, hf = tid & 1;
        const uint4* s0 = (const uint4*)(Qhb + (size_t)r * HD + hf * 32);
        const uint4* s1 = (const uint4*)(Qlb + (size_t)r * HD + hf * 32);
        uint32_t d0 = sQh + r * FROWB + hf * 64;
        uint32_t d1 = sQl + r * FROWB + hf * 64;
#pragma unroll
        for (int i = 0; i < 4; i++) {
            uint4 v = s0[i];
            asm volatile("st.shared.v4.b32 [%0], {%1,%2,%3,%4};"
                         :: "r"(d0 + i * 16), "r"(v.x), "r"(v.y), "r"(v.z), "r"(v.w) : "memory");
            v = s1[i];
            asm volatile("st.shared.v4.b32 [%0], {%1,%2,%3,%4};"
                         :: "r"(d1 + i * 16), "r"(v.x), "r"(v.y), "r"(v.z), "r"(v.w) : "memory");
        }
    }

    const int l8 = lane & 7, mi = lane >> 3;
    const uint32_t qa_off = (uint32_t)(wid * 16 + l8 + ((mi & 1) << 3)) * FROWB
                          + ((mi >> 1) << 4);
    const uint32_t kb_base = (uint32_t)(l8 + ((mi & 1) << 3)) * FROWB + ((mi >> 1) << 4);
    // V trans: row = (mi&1)*8 + l8 within kc block, col block = (mi>>1)
    const uint32_t vb_base = (uint32_t)(((mi & 1) << 3) + l8) * FROWB + ((mi >> 1) << 4);

    float m0 = -1e30f, m1 = -1e30f, l0 = 0.f, l1 = 0.f;
    float o[8][4];
#pragma unroll
    for (int j = 0; j < 8; j++)
#pragma unroll
        for (int v = 0; v < 4; v++) o[j][v] = 0.f;

    const int ntiles = qt + 1;
    for (int kt = 0; kt < ntiles; kt++) {
        __syncthreads();
        {   // load K/V tiles
            const int r = tid >> 1, hf = tid & 1;
            const size_t goff = (size_t)(kt * 64 + r) * HD + hf * 32;
            const uint4* s0 = (const uint4*)(Khb + goff);
            const uint4* s1 = (const uint4*)(Klb + goff);
            const uint4* s2 = (const uint4*)(Vhb + goff);
            const uint4* s3 = (const uint4*)(Vlb + goff);
            const uint32_t dof = r * FROWB + hf * 64;
#pragma unroll
            for (int i = 0; i < 4; i++) {
                uint4 v = s0[i];
                asm volatile("st.shared.v4.b32 [%0], {%1,%2,%3,%4};"
                             :: "r"(sKh + dof + i * 16), "r"(v.x), "r"(v.y), "r"(v.z), "r"(v.w) : "memory");
                v = s1[i];
                asm volatile("st.shared.v4.b32 [%0], {%1,%2,%3,%4};"
                             :: "r"(sKl + dof + i * 16), "r"(v.x), "r"(v.y), "r"(v.z), "r"(v.w) : "memory");
                v = s2[i];
                asm volatile("st.shared.v4.b32 [%0], {%1,%2,%3,%4};"
                             :: "r"(sVh + dof + i * 16), "r"(v.x), "r"(v.y), "r"(v.z), "r"(v.w) : "memory");
                v = s3[i];
                asm volatile("st.shared.v4.b32 [%0], {%1,%2,%3,%4};"
                             :: "r"(sVl + dof + i * 16), "r"(v.x), "r"(v.y), "r"(v.z), "r"(v.w) : "memory");
            }
        }
        __syncthreads();

        // ---- S = Q K^T (64 cols), 3-term split
        float sa[8][4];
#pragma unroll
        for (int j = 0; j < 8; j++)
#pragma unroll
            for (int v = 0; v < 4; v++) sa[j][v] = 0.f;

#pragma unroll
        for (int ks = 0; ks < 4; ks++) {
            uint32_t aqh[4], aql[4];
            ldsm_x4(aqh[0], aqh[1], aqh[2], aqh[3], sQh + qa_off + ks * 32);
            ldsm_x4(aql[0], aql[1], aql[2], aql[3], sQl + qa_off + ks * 32);
#pragma unroll
            for (int p = 0; p < 4; p++) {
                uint32_t addr = kb_base + (uint32_t)(p * 16) * FROWB + ks * 32;
                uint32_t r0, r1, r2, r3;
                uint32_t bh0[2], bh1[2], bl0[2], bl1[2];
                ldsm_x4(r0, r1, r2, r3, sKh + addr);
                bh0[0] = r0; bh0[1] = r2; bh1[0] = r1; bh1[1] = r3;
                ldsm_x4(r0, r1, r2, r3, sKl + addr);
                bl0[0] = r0; bl0[1] = r2; bl1[0] = r1; bl1[1] = r3;
                float* d0 = sa[2 * p];
                float* d1 = sa[2 * p + 1];
                mma_bf16(d0[0], d0[1], d0[2], d0[3], aqh[0], aqh[1], aqh[2], aqh[3], bh0[0], bh0[1]);
                mma_bf16(d0[0], d0[1], d0[2], d0[3], aqh[0], aqh[1], aqh[2], aqh[3], bl0[0], bl0[1]);
                mma_bf16(d0[0], d0[1], d0[2], d0[3], aql[0], aql[1], aql[2], aql[3], bh0[0], bh0[1]);
                mma_bf16(d1[0], d1[1], d1[2], d1[3], aqh[0], aqh[1], aqh[2], aqh[3], bh1[0], bh1[1]);
                mma_bf16(d1[0], d1[1], d1[2], d1[3], aqh[0], aqh[1], aqh[2], aqh[3], bl1[0], bl1[1]);
                mma_bf16(d1[0], d1[1], d1[2], d1[3], aql[0], aql[1], aql[2], aql[3], bh1[0], bh1[1]);
            }
        }

        // ---- scale + causal mask + online softmax
        const bool diag = (kt == qt);
        const int rlo = wid * 16 + (lane >> 2);
        const int rhi = rlo + 8;
        float mx0 = -1e30f, mx1 = -1e30f;
#pragma unroll
        for (int j = 0; j < 8; j++) {
            const int c0 = 8 * j + (lane & 3) * 2;
#pragma unroll
            for (int v = 0; v < 4; v++) {
                float sc = sa[j][v] * 0.125f;
                if (diag) {
                    int col = c0 + (v & 1);
                    int row = (v < 2) ? rlo : rhi;
                    if (col > row) sc = -1e30f;
                }
                sa[j][v] = sc;
            }
            mx0 = fmaxf(mx0, fmaxf(sa[j][0], sa[j][1]));
            mx1 = fmaxf(mx1, fmaxf(sa[j][2], sa[j][3]));
        }
        mx0 = fmaxf(mx0, __shfl_xor_sync(0xffffffffu, mx0, 1));
        mx0 = fmaxf(mx0, __shfl_xor_sync(0xffffffffu, mx0, 2));
        mx1 = fmaxf(mx1, __shfl_xor_sync(0xffffffffu, mx1, 1));
        mx1 = fmaxf(mx1, __shfl_xor_sync(0xffffffffu, mx1, 2));

        const float mn0 = fmaxf(m0, mx0), mn1 = fmaxf(m1, mx1);
        const float al0 = __expf(m0 - mn0), al1 = __expf(m1 - mn1);
        m0 = mn0; m1 = mn1;

        float sum0 = 0.f, sum1 = 0.f;
#pragma unroll
        for (int j = 0; j < 8; j++) {
            float e0 = __expf(sa[j][0] - mn0);
            float e1 = __expf(sa[j][1] - mn0);
            float e2 = __expf(sa[j][2] - mn1);
            float e3 = __expf(sa[j][3] - mn1);
            sa[j][0] = e0; sa[j][1] = e1; sa[j][2] = e2; sa[j][3] = e3;
            sum0 += e0 + e1;
            sum1 += e2 + e3;
        }
        sum0 += __shfl_xor_sync(0xffffffffu, sum0, 1);
        sum0 += __shfl_xor_sync(0xffffffffu, sum0, 2);
        sum1 += __shfl_xor_sync(0xffffffffu, sum1, 1);
        sum1 += __shfl_xor_sync(0xffffffffu, sum1, 2);
        l0 = l0 * al0 + sum0;
        l1 = l1 * al1 + sum1;

#pragma unroll
        for (int j = 0; j < 8; j++) {
            o[j][0] *= al0; o[j][1] *= al0;
            o[j][2] *= al1; o[j][3] *= al1;
        }

        // ---- O += P V, 3-term split (P hi/lo built in regs)
#pragma unroll
        for (int kc = 0; kc < 4; kc++) {
            const float* e0 = sa[2 * kc];
            const float* e1 = sa[2 * kc + 1];
            // hi parts
            uint32_t ph[4], pl[4];
            ph[0] = pack_bf16(e0[0], e0[1]);
            ph[1] = pack_bf16(e0[2], e0[3]);
            ph[2] = pack_bf16(e1[0], e1[1]);
            ph[3] = pack_bf16(e1[2], e1[3]);
            {   // lo parts = e - float(hi)
                __nv_bfloat162 t;
                t = *(__nv_bfloat162*)&ph[0];
                pl[0] = pack_bf16(e0[0] - __bfloat162float(t.x), e0[1] - __bfloat162float(t.y));
                t = *(__nv_bfloat162*)&ph[1];
                pl[1] = pack_bf16(e0[2] - __bfloat162float(t.x), e0[3] - __bfloat162float(t.y));
                t = *(__nv_bfloat162*)&ph[2];
                pl[2] = pack_bf16(e1[0] - __bfloat162float(t.x), e1[1] - __bfloat162float(t.y));
                t = *(__nv_bfloat162*)&ph[3];
                pl[3] = pack_bf16(e1[2] - __bfloat162float(t.x), e1[3] - __bfloat162float(t.y));
            }
#pragma unroll
            for (int t4 = 0; t4 < 4; t4++) {
                uint32_t addr = vb_base + (uint32_t)(kc * 16) * FROWB + t4 * 32;
                uint32_t r0, r1, r2, r3;
                uint32_t bh0[2], bh1[2], bl0[2], bl1[2];
                ldsm_x4_t(r0, r1, r2, r3, sVh + addr);
                bh0[0] = r0; bh0[1] = r1; bh1[0] = r2; bh1[1] = r3;
                ldsm_x4_t(r0, r1, r2, r3, sVl + addr);
                bl0[0] = r0; bl0[1] = r1; bl1[0] = r2; bl1[1] = r3;
                float* d0 = o[2 * t4];
                float* d1 = o[2 * t4 + 1];
                mma_bf16(d0[0], d0[1], d0[2], d0[3], ph[0], ph[1], ph[2], ph[3], bh0[0], bh0[1]);
                mma_bf16(d0[0], d0[1], d0[2], d0[3], pl[0], pl[1], pl[2], pl[3], bh0[0], bh0[1]);
                mma_bf16(d0[0], d0[1], d0[2], d0[3], ph[0], ph[1], ph[2], ph[3], bl0[0], bl0[1]);
                mma_bf16(d1[0], d1[1], d1[2], d1[3], ph[0], ph[1], ph[2], ph[3], bh1[0], bh1[1]);
                mma_bf16(d1[0], d1[1], d1[2], d1[3], pl[0], pl[1], pl[2], pl[3], bh1[0], bh1[1]);
                mma_bf16(d1[0], d1[1], d1[2], d1[3], ph[0], ph[1], ph[2], ph[3], bl1[0], bl1[1]);
            }
        }
    }

    // ---- normalize + write hi/lo bf16 to (B,S,H,D)
    const float inv0 = 1.f / l0, inv1 = 1.f / l1;
    const int rlo = qt * 64 + wid * 16 + (lane >> 2);
    const int rhi = rlo + 8;
#pragma unroll
    for (int j = 0; j < 8; j++) {
        const int d = 8 * j + (lane & 3) * 2;
        size_t plo = ((size_t)(b * SEQ + rlo) * NH + h) * HD + d;
        size_t phi = ((size_t)(b * SEQ + rhi) * NH + h) * HD + d;
        float v0 = o[j][0] * inv0, v1 = o[j][1] * inv0;
        float v2 = o[j][2] * inv1, v3 = o[j][3] * inv1;
        uint32_t h01 = pack_bf16(v0, v1);
        uint32_t h23 = pack_bf16(v2, v3);
        __nv_bfloat162 th;
        th = *(__nv_bfloat162*)&h01;
        uint32_t l01 = pack_bf16(v0 - __bfloat162float(th.x), v1 - __bfloat162float(th.y));
        th = *(__nv_bfloat162*)&h23;
        uint32_t l23 = pack_bf16(v2 - __bfloat162float(th.x), v3 - __bfloat162float(th.y));
        *(uint32_t*)&Oh[plo] = h01;
        *(uint32_t*)&Ol[plo] = l01;
        *(uint32_t*)&Oh[phi] = h23;
        *(uint32_t*)&Ol[phi] = l23;
    }
}

// ---------------- launch -----------------------------------------------------
extern "C" void kernel_launch(void* const* d_in, const int* in_sizes, int n_in,
                              void* d_out, int out_size)
{
    const float* x    = (const float*)d_in[0];
    const float* cosT = (const float*)d_in[2];
    const float* sinT = (const float*)d_in[3];
    const float* Wq   = (const float*)d_in[4];
    const float* Wk   = (const float*)d_in[5];
    const float* Wv   = (const float*)d_in[6];
    const float* Wo   = (const float*)d_in[7];

    float* out = (float*)d_out;                         // (B,S,E)
    float* nk  = out + (size_t)BSZ * SEQ * EMB;         // (B,KV,S,D)
    float* nv  = nk + (size_t)BSZ * NKV * SEQ * HD;     // (B,KV,S,D)

    float *q_lin, *k_lin, *v_lin;
    cudaGetSymbolAddress((void**)&q_lin, g_q_lin);
    cudaGetSymbolAddress((void**)&k_lin, g_k_lin);
    cudaGetSymbolAddress((void**)&v_lin, g_v_lin);

    __nv_bfloat16 *xh, *xl, *ah, *al, *qh, *ql, *kh, *kl, *vh, *vl;
    __nv_bfloat16 *wqh, *wql, *wkh, *wkl, *wvh, *wvl, *woh, *wol;
    cudaGetSymbolAddress((void**)&xh,  g_x_hi);
    cudaGetSymbolAddress((void**)&xl,  g_x_lo);
    cudaGetSymbolAddress((void**)&ah,  g_a_hi);
    cudaGetSymbolAddress((void**)&al,  g_a_lo);
    cudaGetSymbolAddress((void**)&qh,  g_qh);
    cudaGetSymbolAddress((void**)&ql,  g_ql);
    cudaGetSymbolAddress((void**)&kh,  g_kh);
    cudaGetSymbolAddress((void**)&kl,  g_kl);
    cudaGetSymbolAddress((void**)&vh,  g_vh);
    cudaGetSymbolAddress((void**)&vl,  g_vl);
    cudaGetSymbolAddress((void**)&wqh, g_wq_h);
    cudaGetSymbolAddress((void**)&wql, g_wq_l);
    cudaGetSymbolAddress((void**)&wkh, g_wk_h);
    cudaGetSymbolAddress((void**)&wkl, g_wk_l);
    cudaGetSymbolAddress((void**)&wvh, g_wv_h);
    cudaGetSymbolAddress((void**)&wvl, g_wv_l);
    cudaGetSymbolAddress((void**)&woh, g_wo_h);
    cudaGetSymbolAddress((void**)&wol, g_wo_l);

    cudaFuncSetAttribute(gemm_mma_kernel,
                         cudaFuncAttributeMaxDynamicSharedMemorySize, 2 * STAGE_SB);
    cudaFuncSetAttribute(flash_mma_kernel,
                         cudaFuncAttributeMaxDynamicSharedMemorySize, FSMEM);

    const int M = BSZ * SEQ;          // 4096
    const size_t NX = (size_t)M * EMB;

    // split x + weights (transpose+split)
    split_kernel<<<(int)(NX / 4 / 256), 256>>>((const float4*)x, xh, xl);
    wsplit_t_kernel<<<dim3(EMB / 32, EMB / 32), dim3(32, 8)>>>(Wq, wqh, wql, EMB, EMB);
    wsplit_t_kernel<<<dim3(KVD / 32, EMB / 32), dim3(32, 8)>>>(Wk, wkh, wkl, EMB, KVD);
    wsplit_t_kernel<<<dim3(KVD / 32, EMB / 32), dim3(32, 8)>>>(Wv, wvh, wvl, EMB, KVD);
    wsplit_t_kernel<<<dim3(EMB / 32, EMB / 32), dim3(32, 8)>>>(Wo, woh, wol, EMB, EMB);

    // projections on tensor cores (mma.sync bf16, 3-term split)
    gemm_mma_kernel<<<dim3(EMB / 128, M / 128), 256, 2 * STAGE_SB>>>(
        xh, xl, wqh, wql, q_lin, M, EMB, EMB);
    gemm_mma_kernel<<<dim3(KVD / 128, M / 128), 256, 2 * STAGE_SB>>>(
        xh, xl, wkh, wkl, k_lin, M, KVD, EMB);
    gemm_mma_kernel<<<dim3(KVD / 128, M / 128), 256, 2 * STAGE_SB>>>(
        xh, xl, wvh, wvl, v_lin, M, KVD, EMB);

    // rope + layout transforms (fp32 k/v land in d_out; bf16 splits for attn)
    rope_q_kernel<<<(BSZ * SEQ * NH * 32) / 256, 256>>>(q_lin, qh, ql, cosT, sinT);
    rope_k_kernel<<<(BSZ * SEQ * NKV * 32) / 256, 256>>>(k_lin, nk, kh, kl, cosT, sinT);
    vtrans_kernel<<<(BSZ * SEQ * NKV * 16) / 256, 256>>>(
        (const float4*)v_lin, (float4*)nv, vh, vl);

    // attention on tensor cores (writes hi/lo split directly)
    flash_mma_kernel<<<dim3(SEQ / 64, BSZ * NH), 128, FSMEM>>>(
        qh, ql, kh, kl, vh, vl, ah, al);

    // output projection on tensor cores
    gemm_mma_kernel<<<dim3(EMB / 128, M / 128), 256, 2 * STAGE_SB>>>(
        ah, al, woh, wol, out, M, EMB, EMB);
}

// round 9
// speedup vs baseline: 2.3209x; 1.0898x over previous
#include <cuda_runtime.h>
#include <cuda_bf16.h>
#include <math.h>
#include <stdint.h>

#define BSZ 2
#define SEQ 2048
#define EMB 2048
#define NH  32
#define NKV 8
#define HD  64
#define KVD (NKV * HD)   // 512
#define QKVN (EMB + 2 * KVD)   // 3072

// ---------------- scratch (static device memory; no allocs allowed) ----------
__device__ float g_qkv_lin[BSZ * SEQ * QKVN];       // x@[Wq|Wk|Wv] (B,S,3072)

// bf16 split buffers
__device__ __nv_bfloat16 g_x_hi[BSZ * SEQ * EMB];
__device__ __nv_bfloat16 g_x_lo[BSZ * SEQ * EMB];
__device__ __nv_bfloat16 g_a_hi[BSZ * SEQ * EMB];   // attn out hi (B,S,H,D)
__device__ __nv_bfloat16 g_a_lo[BSZ * SEQ * EMB];   // attn out lo
__device__ __nv_bfloat16 g_qh[BSZ * SEQ * EMB];     // rope'd q hi (B,H,S,D)
__device__ __nv_bfloat16 g_ql[BSZ * SEQ * EMB];
__device__ __nv_bfloat16 g_kh[BSZ * SEQ * KVD];     // rope'd k hi (B,KV,S,D)
__device__ __nv_bfloat16 g_kl[BSZ * SEQ * KVD];
__device__ __nv_bfloat16 g_vh[BSZ * SEQ * KVD];     // v hi (B,KV,S,D)
__device__ __nv_bfloat16 g_vl[BSZ * SEQ * KVD];
__device__ __nv_bfloat16 g_wqkv_h[QKVN * EMB];      // packed [Wq;Wk;Wv]^T hi
__device__ __nv_bfloat16 g_wqkv_l[QKVN * EMB];
__device__ __nv_bfloat16 g_wo_h[EMB * EMB];
__device__ __nv_bfloat16 g_wo_l[EMB * EMB];

// ======================= helpers =============================================
__device__ __forceinline__ uint32_t cvta_smem(const void* p) {
    uint32_t a;
    asm("{ .reg .u64 t; cvta.to.shared.u64 t, %1; cvt.u32.u64 %0, t; }"
        : "=r"(a) : "l"(p));
    return a;
}

__device__ __forceinline__ void cp16(uint32_t dst, const void* src) {
    asm volatile("cp.async.cg.shared.global [%0], [%1], 16;"
                 :: "r"(dst), "l"(src) : "memory");
}
#define CP_COMMIT() asm volatile("cp.async.commit_group;" ::: "memory")
#define CP_WAIT(n)  asm volatile("cp.async.wait_group %0;" :: "n"(n) : "memory")

__device__ __forceinline__ void ldsm_x4(uint32_t& r0, uint32_t& r1,
                                        uint32_t& r2, uint32_t& r3, uint32_t addr) {
    asm volatile("ldmatrix.sync.aligned.m8n8.x4.shared.b16 {%0,%1,%2,%3}, [%4];"
                 : "=r"(r0), "=r"(r1), "=r"(r2), "=r"(r3) : "r"(addr));
}

__device__ __forceinline__ void ldsm_x4_t(uint32_t& r0, uint32_t& r1,
                                          uint32_t& r2, uint32_t& r3, uint32_t addr) {
    asm volatile("ldmatrix.sync.aligned.m8n8.x4.trans.shared.b16 {%0,%1,%2,%3}, [%4];"
                 : "=r"(r0), "=r"(r1), "=r"(r2), "=r"(r3) : "r"(addr));
}

__device__ __forceinline__ void mma_bf16(float& d0, float& d1, float& d2, float& d3,
                                         uint32_t a0, uint32_t a1, uint32_t a2, uint32_t a3,
                                         uint32_t b0, uint32_t b1) {
    asm volatile(
        "mma.sync.aligned.m16n8k16.row.col.f32.bf16.bf16.f32 "
        "{%0,%1,%2,%3}, {%4,%5,%6,%7}, {%8,%9}, {%0,%1,%2,%3};"
        : "+f"(d0), "+f"(d1), "+f"(d2), "+f"(d3)
        : "r"(a0), "r"(a1), "r"(a2), "r"(a3), "r"(b0), "r"(b1));
}

__device__ __forceinline__ uint32_t pack_bf16(float a, float b) {
    __nv_bfloat162 t(__float2bfloat16(a), __float2bfloat16(b));
    return *(uint32_t*)&t;
}

// ============ split conversion: fp32 -> (hi bf16, lo bf16) ===================
__global__ void split_kernel(const float4* __restrict__ in,
                             __nv_bfloat16* __restrict__ hi,
                             __nv_bfloat16* __restrict__ lo)
{
    int i = blockIdx.x * blockDim.x + threadIdx.x;
    float4 v = in[i];
    __nv_bfloat16 h[4], l[4];
    h[0] = __float2bfloat16(v.x); l[0] = __float2bfloat16(v.x - __bfloat162float(h[0]));
    h[1] = __float2bfloat16(v.y); l[1] = __float2bfloat16(v.y - __bfloat162float(h[1]));
    h[2] = __float2bfloat16(v.z); l[2] = __float2bfloat16(v.z - __bfloat162float(h[2]));
    h[3] = __float2bfloat16(v.w); l[3] = __float2bfloat16(v.w - __bfloat162float(h[3]));
    *(uint2*)&hi[(size_t)i * 4] = *(uint2*)h;
    *(uint2*)&lo[(size_t)i * 4] = *(uint2*)l;
}

// ===== weight transpose + split: W[K,N] fp32 -> Wt_hi/lo [N,K] bf16 ==========
__global__ void wsplit_t_kernel(const float* __restrict__ W,
                                __nv_bfloat16* __restrict__ Th,
                                __nv_bfloat16* __restrict__ Tl,
                                int K, int N)
{
    __shared__ float tile[32][33];
    int n0 = blockIdx.x * 32, k0 = blockIdx.y * 32;
    int tx = threadIdx.x, ty = threadIdx.y;   // 32 x 8
#pragma unroll
    for (int i = 0; i < 4; i++)
        tile[ty + 8 * i][tx] = W[(size_t)(k0 + ty + 8 * i) * N + n0 + tx];
    __syncthreads();
#pragma unroll
    for (int i = 0; i < 4; i++) {
        float v = tile[tx][ty + 8 * i];
        __nv_bfloat16 h = __float2bfloat16(v);
        __nv_bfloat16 l = __float2bfloat16(v - __bfloat162float(h));
        size_t o = (size_t)(n0 + ty + 8 * i) * K + k0 + tx;
        Th[o] = h;
        Tl[o] = l;
    }
}

// ====== mma.sync GEMM: C[M,N] = A[M,K] @ W[K,N], 3-term bf16 split ===========
// cp.async 2-stage pipeline. CTA 128x128, BK=32, 256 threads (2x4 warps).
#define ROWB 80
#define TILE_SB (128 * ROWB)
#define STAGE_SB (4 * TILE_SB)

__global__ void __launch_bounds__(256) gemm_mma_kernel(
    const __nv_bfloat16* __restrict__ Ah, const __nv_bfloat16* __restrict__ Al,
    const __nv_bfloat16* __restrict__ Bh, const __nv_bfloat16* __restrict__ Bl,
    float* __restrict__ C, int M, int N, int K)
{
    extern __shared__ char dsm[];
    const int tid = threadIdx.x;
    const int wid = tid >> 5, lane = tid & 31;
    const int wm = wid >> 2, wn = wid & 3;
    const int mT = blockIdx.y, nT = blockIdx.x;

    const uint32_t sbase = cvta_smem(dsm);

    const int gr  = tid >> 1;
    const int gk  = (tid & 1) * 2;
    const __nv_bfloat16* srcs[4] = {
        Ah + (size_t)(mT * 128 + gr) * K + gk * 8,
        Al + (size_t)(mT * 128 + gr) * K + gk * 8,
        Bh + (size_t)(nT * 128 + gr) * K + gk * 8,
        Bl + (size_t)(nT * 128 + gr) * K + gk * 8
    };
    const uint32_t sdst = gr * ROWB + gk * 16;

    float acc[4][4][4];
#pragma unroll
    for (int i = 0; i < 4; i++)
#pragma unroll
        for (int j = 0; j < 4; j++)
#pragma unroll
            for (int v = 0; v < 4; v++) acc[i][j][v] = 0.f;

    const int l8 = lane & 7, mi = lane >> 3;
    const uint32_t a_off = (uint32_t)(wm * 64 + l8 + ((mi & 1) << 3)) * ROWB
                         + ((mi >> 1) << 3) * 2;
    const uint32_t b_off = (uint32_t)(wn * 32 + l8 + ((mi & 1) << 3)) * ROWB
                         + ((mi >> 1) << 3) * 2;

    const int nch = K >> 5;

    // prologue: async-load stage 0
#pragma unroll
    for (int t = 0; t < 4; t++) {
        uint32_t a = sbase + t * TILE_SB + sdst;
        cp16(a, srcs[t]);
        cp16(a + 16, srcs[t] + 8);
    }
    CP_COMMIT();

    for (int ch = 0; ch < nch; ch++) {
        const uint32_t stage = sbase + (ch & 1) * STAGE_SB;
        const bool more = (ch + 1 < nch);

        if (more) {
            const int k0 = (ch + 1) << 5;
            const uint32_t nstage = sbase + ((ch + 1) & 1) * STAGE_SB;
#pragma unroll
            for (int t = 0; t < 4; t++) {
                uint32_t a = nstage + t * TILE_SB + sdst;
                cp16(a, srcs[t] + k0);
                cp16(a + 16, srcs[t] + k0 + 8);
            }
            CP_COMMIT();
            CP_WAIT(1);           // stage ch is complete
        } else {
            CP_WAIT(0);
        }
        __syncthreads();

#pragma unroll
        for (int k16 = 0; k16 < 2; k16++) {
            const uint32_t kb = k16 * 32;
            uint32_t ah[4][4], al[4][4];
#pragma unroll
            for (int i = 0; i < 4; i++) {
                uint32_t addr = stage + a_off + (uint32_t)(i * 16) * ROWB + kb;
                ldsm_x4(ah[i][0], ah[i][1], ah[i][2], ah[i][3], addr);
                ldsm_x4(al[i][0], al[i][1], al[i][2], al[i][3], addr + TILE_SB);
            }
            uint32_t bh[4][2], bl[4][2];
#pragma unroll
            for (int p = 0; p < 2; p++) {
                uint32_t addr = stage + 2 * TILE_SB + b_off + (uint32_t)(p * 16) * ROWB + kb;
                uint32_t r0, r1, r2, r3;
                ldsm_x4(r0, r1, r2, r3, addr);
                bh[2 * p][0] = r0; bh[2 * p][1] = r2;
                bh[2 * p + 1][0] = r1; bh[2 * p + 1][1] = r3;
                ldsm_x4(r0, r1, r2, r3, addr + TILE_SB);
                bl[2 * p][0] = r0; bl[2 * p][1] = r2;
                bl[2 * p + 1][0] = r1; bl[2 * p + 1][1] = r3;
            }
#pragma unroll
            for (int i = 0; i < 4; i++)
#pragma unroll
                for (int j = 0; j < 4; j++) {
                    float* d = acc[i][j];
                    mma_bf16(d[0], d[1], d[2], d[3],
                             ah[i][0], ah[i][1], ah[i][2], ah[i][3],
                             bh[j][0], bh[j][1]);
                    mma_bf16(d[0], d[1], d[2], d[3],
                             ah[i][0], ah[i][1], ah[i][2], ah[i][3],
                             bl[j][0], bl[j][1]);
                    mma_bf16(d[0], d[1], d[2], d[3],
                             al[i][0], al[i][1], al[i][2], al[i][3],
                             bh[j][0], bh[j][1]);
                }
        }
        __syncthreads();   // all warps done reading before buffer is overwritten
    }

    const int er = lane >> 2, ec = (lane & 3) * 2;
    float* Cb = C + (size_t)(mT * 128 + wm * 64 + er) * N + nT * 128 + wn * 32 + ec;
#pragma unroll
    for (int i = 0; i < 4; i++)
#pragma unroll
        for (int j = 0; j < 4; j++) {
            float* p0 = Cb + (size_t)(i * 16) * N + j * 8;
            *(float2*)p0                      = make_float2(acc[i][j][0], acc[i][j][1]);
            *(float2*)(p0 + (size_t)8 * N)    = make_float2(acc[i][j][2], acc[i][j][3]);
        }
}

// -------- RoPE q: qkv (B,S,3072) fp32 -> (B,H,S,D) bf16 hi/lo ---------------
__global__ void rope_q_kernel(const float* __restrict__ qkv,
                              __nv_bfloat16* __restrict__ qh,
                              __nv_bfloat16* __restrict__ ql,
                              const float* __restrict__ cosT, const float* __restrict__ sinT)
{
    int idx = blockIdx.x * blockDim.x + threadIdx.x;
    int d = idx & 31;
    int h = (idx >> 5) & 31;
    int s = (idx >> 10) & 2047;
    int b = idx >> 21;
    float cv = cosT[s * HD + d];
    float sv = sinT[s * HD + d];
    size_t i0 = (size_t)(b * SEQ + s) * QKVN + h * HD + d;
    float x1 = qkv[i0], x2 = qkv[i0 + 32];
    float v1 = x1 * cv - x2 * sv;
    float v2 = x2 * cv + x1 * sv;
    size_t o0 = ((size_t)(b * NH + h) * SEQ + s) * HD + d;
    __nv_bfloat16 h1 = __float2bfloat16(v1);
    __nv_bfloat16 h2 = __float2bfloat16(v2);
    qh[o0]      = h1;
    qh[o0 + 32] = h2;
    ql[o0]      = __float2bfloat16(v1 - __bfloat162float(h1));
    ql[o0 + 32] = __float2bfloat16(v2 - __bfloat162float(h2));
}

// ---- RoPE k: qkv (B,S,3072) -> fp32 next_k + bf16 hi/lo (B,KV,S,D) ---------
__global__ void rope_k_kernel(const float* __restrict__ qkv, float* __restrict__ kout,
                              __nv_bfloat16* __restrict__ kh,
                              __nv_bfloat16* __restrict__ kl,
                              const float* __restrict__ cosT, const float* __restrict__ sinT)
{
    int idx = blockIdx.x * blockDim.x + threadIdx.x;
    int d = idx & 31;
    int h = (idx >> 5) & 7;
    int s = (idx >> 8) & 2047;
    int b = idx >> 19;
    float cv = cosT[s * HD + d];
    float sv = sinT[s * HD + d];
    size_t i0 = (size_t)(b * SEQ + s) * QKVN + EMB + h * HD + d;
    float x1 = qkv[i0], x2 = qkv[i0 + 32];
    float v1 = x1 * cv - x2 * sv;
    float v2 = x2 * cv + x1 * sv;
    size_t o0 = ((size_t)(b * NKV + h) * SEQ + s) * HD + d;
    kout[o0]      = v1;
    kout[o0 + 32] = v2;
    __nv_bfloat16 h1 = __float2bfloat16(v1);
    __nv_bfloat16 h2 = __float2bfloat16(v2);
    kh[o0]      = h1;
    kh[o0 + 32] = h2;
    kl[o0]      = __float2bfloat16(v1 - __bfloat162float(h1));
    kl[o0 + 32] = __float2bfloat16(v2 - __bfloat162float(h2));
}

// -- V transpose: qkv (B,S,3072) -> fp32 next_v + bf16 hi/lo (B,KV,S,D) ------
__global__ void vtrans_kernel(const float4* __restrict__ qkv4, float4* __restrict__ vout,
                              __nv_bfloat16* __restrict__ vh,
                              __nv_bfloat16* __restrict__ vl)
{
    int idx = blockIdx.x * blockDim.x + threadIdx.x;
    int f = idx & 15;
    int h = (idx >> 4) & 7;
    int s = (idx >> 7) & 2047;
    int b = idx >> 18;
    float4 v = qkv4[(size_t)(b * SEQ + s) * (QKVN / 4) + (EMB + KVD) / 4 + h * 16 + f];
    size_t o = ((size_t)(b * NKV + h) * SEQ + s) * (HD / 4) + f;
    vout[o] = v;
    __nv_bfloat16 hh[4], ll[4];
    hh[0] = __float2bfloat16(v.x); ll[0] = __float2bfloat16(v.x - __bfloat162float(hh[0]));
    hh[1] = __float2bfloat16(v.y); ll[1] = __float2bfloat16(v.y - __bfloat162float(hh[1]));
    hh[2] = __float2bfloat16(v.z); ll[2] = __float2bfloat16(v.z - __bfloat162float(hh[2]));
    hh[3] = __float2bfloat16(v.w); ll[3] = __float2bfloat16(v.w - __bfloat162float(hh[3]));
    *(uint2*)&vh[o * 4] = *(uint2*)hh;
    *(uint2*)&vl[o * 4] = *(uint2*)ll;
}

// ---------------- causal flash attention (mma.sync bf16 split) ---------------
#define FROWB  144
#define FTILE  (64 * FROWB)
#define FSMEM  (6 * FTILE)

__global__ void __launch_bounds__(128) flash_mma_kernel(
    const __nv_bfloat16* __restrict__ Qh, const __nv_bfloat16* __restrict__ Ql,
    const __nv_bfloat16* __restrict__ Kh, const __nv_bfloat16* __restrict__ Kl,
    const __nv_bfloat16* __restrict__ Vh, const __nv_bfloat16* __restrict__ Vl,
    __nv_bfloat16* __restrict__ Oh, __nv_bfloat16* __restrict__ Ol)
{
    extern __shared__ char fsm[];
    const uint32_t sb  = cvta_smem(fsm);
    const uint32_t sQh = sb, sQl = sb + FTILE;
    const uint32_t sKh = sb + 2 * FTILE, sKl = sb + 3 * FTILE;
    const uint32_t sVh = sb + 4 * FTILE, sVl = sb + 5 * FTILE;

    const int qt = blockIdx.x, hh = blockIdx.y;
    const int b = hh >> 5, h = hh & 31, kvh = h >> 2;
    const int tid = threadIdx.x, wid = tid >> 5, lane = tid & 31;

    const __nv_bfloat16* Qhb = Qh + ((size_t)((b * NH + h) * SEQ) + qt * 64) * HD;
    const __nv_bfloat16* Qlb = Ql + ((size_t)((b * NH + h) * SEQ) + qt * 64) * HD;
    const __nv_bfloat16* Khb = Kh + (size_t)((b * NKV + kvh) * SEQ) * HD;
    const __nv_bfloat16* Klb = Kl + (size_t)((b * NKV + kvh) * SEQ) * HD;
    const __nv_bfloat16* Vhb = Vh + (size_t)((b * NKV + kvh) * SEQ) * HD;
    const __nv_bfloat16* Vlb = Vl + (size_t)((b * NKV + kvh) * SEQ) * HD;

    {
        const int r = tid >> 1, hf = tid & 1;
        const uint4* s0 = (const uint4*)(Qhb + (size_t)r * HD + hf * 32);
        const uint4* s1 = (const uint4*)(Qlb + (size_t)r * HD + hf * 32);
        uint32_t d0 = sQh + r * FROWB + hf * 64;
        uint32_t d1 = sQl + r * FROWB + hf * 64;
#pragma unroll
        for (int i = 0; i < 4; i++) {
            uint4 v = s0[i];
            asm volatile("st.shared.v4.b32 [%0], {%1,%2,%3,%4};"
                         :: "r"(d0 + i * 16), "r"(v.x), "r"(v.y), "r"(v.z), "r"(v.w) : "memory");
            v = s1[i];
            asm volatile("st.shared.v4.b32 [%0], {%1,%2,%3,%4};"
                         :: "r"(d1 + i * 16), "r"(v.x), "r"(v.y), "r"(v.z), "r"(v.w) : "memory");
        }
    }

    const int l8 = lane & 7, mi = lane >> 3;
    const uint32_t qa_off = (uint32_t)(wid * 16 + l8 + ((mi & 1) << 3)) * FROWB
                          + ((mi >> 1) << 4);
    const uint32_t kb_base = (uint32_t)(l8 + ((mi & 1) << 3)) * FROWB + ((mi >> 1) << 4);
    const uint32_t vb_base = (uint32_t)(((mi & 1) << 3) + l8) * FROWB + ((mi >> 1) << 4);

    float m0 = -1e30f, m1 = -1e30f, l0 = 0.f, l1 = 0.f;
    float o[8][4];
#pragma unroll
    for (int j = 0; j < 8; j++)
#pragma unroll
        for (int v = 0; v < 4; v++) o[j][v] = 0.f;

    const int ntiles = qt + 1;
    for (int kt = 0; kt < ntiles; kt++) {
        __syncthreads();
        {
            const int r = tid >> 1, hf = tid & 1;
            const size_t goff = (size_t)(kt * 64 + r) * HD + hf * 32;
            const uint4* s0 = (const uint4*)(Khb + goff);
            const uint4* s1 = (const uint4*)(Klb + goff);
            const uint4* s2 = (const uint4*)(Vhb + goff);
            const uint4* s3 = (const uint4*)(Vlb + goff);
            const uint32_t dof = r * FROWB + hf * 64;
#pragma unroll
            for (int i = 0; i < 4; i++) {
                uint4 v = s0[i];
                asm volatile("st.shared.v4.b32 [%0], {%1,%2,%3,%4};"
                             :: "r"(sKh + dof + i * 16), "r"(v.x), "r"(v.y), "r"(v.z), "r"(v.w) : "memory");
                v = s1[i];
                asm volatile("st.shared.v4.b32 [%0], {%1,%2,%3,%4};"
                             :: "r"(sKl + dof + i * 16), "r"(v.x), "r"(v.y), "r"(v.z), "r"(v.w) : "memory");
                v = s2[i];
                asm volatile("st.shared.v4.b32 [%0], {%1,%2,%3,%4};"
                             :: "r"(sVh + dof + i * 16), "r"(v.x), "r"(v.y), "r"(v.z), "r"(v.w) : "memory");
                v = s3[i];
                asm volatile("st.shared.v4.b32 [%0], {%1,%2,%3,%4};"
                             :: "r"(sVl + dof + i * 16), "r"(v.x), "r"(v.y), "r"(v.z), "r"(v.w) : "memory");
            }
        }
        __syncthreads();

        float sa[8][4];
#pragma unroll
        for (int j = 0; j < 8; j++)
#pragma unroll
            for (int v = 0; v < 4; v++) sa[j][v] = 0.f;

#pragma unroll
        for (int ks = 0; ks < 4; ks++) {
            uint32_t aqh[4], aql[4];
            ldsm_x4(aqh[0], aqh[1], aqh[2], aqh[3], sQh + qa_off + ks * 32);
            ldsm_x4(aql[0], aql[1], aql[2], aql[3], sQl + qa_off + ks * 32);
#pragma unroll
            for (int p = 0; p < 4; p++) {
                uint32_t addr = kb_base + (uint32_t)(p * 16) * FROWB + ks * 32;
                uint32_t r0, r1, r2, r3;
                uint32_t bh0[2], bh1[2], bl0[2], bl1[2];
                ldsm_x4(r0, r1, r2, r3, sKh + addr);
                bh0[0] = r0; bh0[1] = r2; bh1[0] = r1; bh1[1] = r3;
                ldsm_x4(r0, r1, r2, r3, sKl + addr);
                bl0[0] = r0; bl0[1] = r2; bl1[0] = r1; bl1[1] = r3;
                float* d0 = sa[2 * p];
                float* d1 = sa[2 * p + 1];
                mma_bf16(d0[0], d0[1], d0[2], d0[3], aqh[0], aqh[1], aqh[2], aqh[3], bh0[0], bh0[1]);
                mma_bf16(d0[0], d0[1], d0[2], d0[3], aqh[0], aqh[1], aqh[2], aqh[3], bl0[0], bl0[1]);
                mma_bf16(d0[0], d0[1], d0[2], d0[3], aql[0], aql[1], aql[2], aql[3], bh0[0], bh0[1]);
                mma_bf16(d1[0], d1[1], d1[2], d1[3], aqh[0], aqh[1], aqh[2], aqh[3], bh1[0], bh1[1]);
                mma_bf16(d1[0], d1[1], d1[2], d1[3], aqh[0], aqh[1], aqh[2], aqh[3], bl1[0], bl1[1]);
                mma_bf16(d1[0], d1[1], d1[2], d1[3], aql[0], aql[1], aql[2], aql[3], bh1[0], bh1[1]);
            }
        }

        const bool diag = (kt == qt);
        const int rlo = wid * 16 + (lane >> 2);
        const int rhi = rlo + 8;
        float mx0 = -1e30f, mx1 = -1e30f;
#pragma unroll
        for (int j = 0; j < 8; j++) {
            const int c0 = 8 * j + (lane & 3) * 2;
#pragma unroll
            for (int v = 0; v < 4; v++) {
                float sc = sa[j][v] * 0.125f;
                if (diag) {
                    int col = c0 + (v & 1);
                    int row = (v < 2) ? rlo : rhi;
                    if (col > row) sc = -1e30f;
                }
                sa[j][v] = sc;
            }
            mx0 = fmaxf(mx0, fmaxf(sa[j][0], sa[j][1]));
            mx1 = fmaxf(mx1, fmaxf(sa[j][2], sa[j][3]));
        }
        mx0 = fmaxf(mx0, __shfl_xor_sync(0xffffffffu, mx0, 1));
        mx0 = fmaxf(mx0, __shfl_xor_sync(0xffffffffu, mx0, 2));
        mx1 = fmaxf(mx1, __shfl_xor_sync(0xffffffffu, mx1, 1));
        mx1 = fmaxf(mx1, __shfl_xor_sync(0xffffffffu, mx1, 2));

        const float mn0 = fmaxf(m0, mx0), mn1 = fmaxf(m1, mx1);
        const float al0 = __expf(m0 - mn0), al1 = __expf(m1 - mn1);
        m0 = mn0; m1 = mn1;

        float sum0 = 0.f, sum1 = 0.f;
#pragma unroll
        for (int j = 0; j < 8; j++) {
            float e0 = __expf(sa[j][0] - mn0);
            float e1 = __expf(sa[j][1] - mn0);
            float e2 = __expf(sa[j][2] - mn1);
            float e3 = __expf(sa[j][3] - mn1);
            sa[j][0] = e0; sa[j][1] = e1; sa[j][2] = e2; sa[j][3] = e3;
            sum0 += e0 + e1;
            sum1 += e2 + e3;
        }
        sum0 += __shfl_xor_sync(0xffffffffu, sum0, 1);
        sum0 += __shfl_xor_sync(0xffffffffu, sum0, 2);
        sum1 += __shfl_xor_sync(0xffffffffu, sum1, 1);
        sum1 += __shfl_xor_sync(0xffffffffu, sum1, 2);
        l0 = l0 * al0 + sum0;
        l1 = l1 * al1 + sum1;

#pragma unroll
        for (int j = 0; j < 8; j++) {
            o[j][0] *= al0; o[j][1] *= al0;
            o[j][2] *= al1; o[j][3] *= al1;
        }

#pragma unroll
        for (int kc = 0; kc < 4; kc++) {
            const float* e0 = sa[2 * kc];
            const float* e1 = sa[2 * kc + 1];
            uint32_t ph[4], pl[4];
            ph[0] = pack_bf16(e0[0], e0[1]);
            ph[1] = pack_bf16(e0[2], e0[3]);
            ph[2] = pack_bf16(e1[0], e1[1]);
            ph[3] = pack_bf16(e1[2], e1[3]);
            {
                __nv_bfloat162 t;
                t = *(__nv_bfloat162*)&ph[0];
                pl[0] = pack_bf16(e0[0] - __bfloat162float(t.x), e0[1] - __bfloat162float(t.y));
                t = *(__nv_bfloat162*)&ph[1];
                pl[1] = pack_bf16(e0[2] - __bfloat162float(t.x), e0[3] - __bfloat162float(t.y));
                t = *(__nv_bfloat162*)&ph[2];
                pl[2] = pack_bf16(e1[0] - __bfloat162float(t.x), e1[1] - __bfloat162float(t.y));
                t = *(__nv_bfloat162*)&ph[3];
                pl[3] = pack_bf16(e1[2] - __bfloat162float(t.x), e1[3] - __bfloat162float(t.y));
            }
#pragma unroll
            for (int t4 = 0; t4 < 4; t4++) {
                uint32_t addr = vb_base + (uint32_t)(kc * 16) * FROWB + t4 * 32;
                uint32_t r0, r1, r2, r3;
                uint32_t bh0[2], bh1[2], bl0[2], bl1[2];
                ldsm_x4_t(r0, r1, r2, r3, sVh + addr);
                bh0[0] = r0; bh0[1] = r1; bh1[0] = r2; bh1[1] = r3;
                ldsm_x4_t(r0, r1, r2, r3, sVl + addr);
                bl0[0] = r0; bl0[1] = r1; bl1[0] = r2; bl1[1] = r3;
                float* d0 = o[2 * t4];
                float* d1 = o[2 * t4 + 1];
                mma_bf16(d0[0], d0[1], d0[2], d0[3], ph[0], ph[1], ph[2], ph[3], bh0[0], bh0[1]);
                mma_bf16(d0[0], d0[1], d0[2], d0[3], pl[0], pl[1], pl[2], pl[3], bh0[0], bh0[1]);
                mma_bf16(d0[0], d0[1], d0[2], d0[3], ph[0], ph[1], ph[2], ph[3], bl0[0], bl0[1]);
                mma_bf16(d1[0], d1[1], d1[2], d1[3], ph[0], ph[1], ph[2], ph[3], bh1[0], bh1[1]);
                mma_bf16(d1[0], d1[1], d1[2], d1[3], pl[0], pl[1], pl[2], pl[3], bh1[0], bh1[1]);
                mma_bf16(d1[0], d1[1], d1[2], d1[3], ph[0], ph[1], ph[2], ph[3], bl1[0], bl1[1]);
            }
        }
    }

    const float inv0 = 1.f / l0, inv1 = 1.f / l1;
    const int rlo = qt * 64 + wid * 16 + (lane >> 2);
    const int rhi = rlo + 8;
#pragma unroll
    for (int j = 0; j < 8; j++) {
        const int d = 8 * j + (lane & 3) * 2;
        size_t plo = ((size_t)(b * SEQ + rlo) * NH + h) * HD + d;
        size_t phi = ((size_t)(b * SEQ + rhi) * NH + h) * HD + d;
        float v0 = o[j][0] * inv0, v1 = o[j][1] * inv0;
        float v2 = o[j][2] * inv1, v3 = o[j][3] * inv1;
        uint32_t h01 = pack_bf16(v0, v1);
        uint32_t h23 = pack_bf16(v2, v3);
        __nv_bfloat162 th;
        th = *(__nv_bfloat162*)&h01;
        uint32_t l01 = pack_bf16(v0 - __bfloat162float(th.x), v1 - __bfloat162float(th.y));
        th = *(__nv_bfloat162*)&h23;
        uint32_t l23 = pack_bf16(v2 - __bfloat162float(th.x), v3 - __bfloat162float(th.y));
        *(uint32_t*)&Oh[plo] = h01;
        *(uint32_t*)&Ol[plo] = l01;
        *(uint32_t*)&Oh[phi] = h23;
        *(uint32_t*)&Ol[phi] = l23;
    }
}

// ---------------- launch -----------------------------------------------------
extern "C" void kernel_launch(void* const* d_in, const int* in_sizes, int n_in,
                              void* d_out, int out_size)
{
    const float* x    = (const float*)d_in[0];
    const float* cosT = (const float*)d_in[2];
    const float* sinT = (const float*)d_in[3];
    const float* Wq   = (const float*)d_in[4];
    const float* Wk   = (const float*)d_in[5];
    const float* Wv   = (const float*)d_in[6];
    const float* Wo   = (const float*)d_in[7];

    float* out = (float*)d_out;                         // (B,S,E)
    float* nk  = out + (size_t)BSZ * SEQ * EMB;         // (B,KV,S,D)
    float* nv  = nk + (size_t)BSZ * NKV * SEQ * HD;     // (B,KV,S,D)

    float* qkv_lin;
    cudaGetSymbolAddress((void**)&qkv_lin, g_qkv_lin);

    __nv_bfloat16 *xh, *xl, *ah, *al, *qh, *ql, *kh, *kl, *vh, *vl;
    __nv_bfloat16 *wqkvh, *wqkvl, *woh, *wol;
    cudaGetSymbolAddress((void**)&xh,  g_x_hi);
    cudaGetSymbolAddress((void**)&xl,  g_x_lo);
    cudaGetSymbolAddress((void**)&ah,  g_a_hi);
    cudaGetSymbolAddress((void**)&al,  g_a_lo);
    cudaGetSymbolAddress((void**)&qh,  g_qh);
    cudaGetSymbolAddress((void**)&ql,  g_ql);
    cudaGetSymbolAddress((void**)&kh,  g_kh);
    cudaGetSymbolAddress((void**)&kl,  g_kl);
    cudaGetSymbolAddress((void**)&vh,  g_vh);
    cudaGetSymbolAddress((void**)&vl,  g_vl);
    cudaGetSymbolAddress((void**)&wqkvh, g_wqkv_h);
    cudaGetSymbolAddress((void**)&wqkvl, g_wqkv_l);
    cudaGetSymbolAddress((void**)&woh, g_wo_h);
    cudaGetSymbolAddress((void**)&wol, g_wo_l);

    cudaFuncSetAttribute(gemm_mma_kernel,
                         cudaFuncAttributeMaxDynamicSharedMemorySize, 2 * STAGE_SB);
    cudaFuncSetAttribute(flash_mma_kernel,
                         cudaFuncAttributeMaxDynamicSharedMemorySize, FSMEM);

    const int M = BSZ * SEQ;          // 4096
    const size_t NX = (size_t)M * EMB;

    // split x + weights (transpose+split; QKV packed row-wise [3072 x 2048])
    split_kernel<<<(int)(NX / 4 / 256), 256>>>((const float4*)x, xh, xl);
    wsplit_t_kernel<<<dim3(EMB / 32, EMB / 32), dim3(32, 8)>>>(Wq, wqkvh, wqkvl, EMB, EMB);
    wsplit_t_kernel<<<dim3(KVD / 32, EMB / 32), dim3(32, 8)>>>(
        Wk, wqkvh + (size_t)EMB * EMB, wqkvl + (size_t)EMB * EMB, EMB, KVD);
    wsplit_t_kernel<<<dim3(KVD / 32, EMB / 32), dim3(32, 8)>>>(
        Wv, wqkvh + (size_t)(EMB + KVD) * EMB, wqkvl + (size_t)(EMB + KVD) * EMB, EMB, KVD);
    wsplit_t_kernel<<<dim3(EMB / 32, EMB / 32), dim3(32, 8)>>>(Wo, woh, wol, EMB, EMB);

    // fused QKV projection on tensor cores
    gemm_mma_kernel<<<dim3(QKVN / 128, M / 128), 256, 2 * STAGE_SB>>>(
        xh, xl, wqkvh, wqkvl, qkv_lin, M, QKVN, EMB);

    // rope + layout transforms (fp32 k/v land in d_out; bf16 splits for attn)
    rope_q_kernel<<<(BSZ * SEQ * NH * 32) / 256, 256>>>(qkv_lin, qh, ql, cosT, sinT);
    rope_k_kernel<<<(BSZ * SEQ * NKV * 32) / 256, 256>>>(qkv_lin, nk, kh, kl, cosT, sinT);
    vtrans_kernel<<<(BSZ * SEQ * NKV * 16) / 256, 256>>>(
        (const float4*)qkv_lin, (float4*)nv, vh, vl);

    // attention on tensor cores (writes hi/lo split directly)
    flash_mma_kernel<<<dim3(SEQ / 64, BSZ * NH), 128, FSMEM>>>(
        qh, ql, kh, kl, vh, vl, ah, al);

    // output projection on tensor cores
    gemm_mma_kernel<<<dim3(EMB / 128, M / 128), 256, 2 * STAGE_SB>>>(
        ah, al, woh, wol, out, M, EMB, EMB);
}